// round 4
// baseline (speedup 1.0000x reference)
#include <cuda_runtime.h>
#include <math.h>

#define BB 32
#define TT 512
#define CCH 512
#define HHD 512
#define G4 2048
#define MR (BB*TT)   // 16384

#define UPB 8          // hidden units per recurrence block
#define NBLK 128       // recurrence blocks (64 per direction)
#define GEMM_NBLK 4096
#define TOTAL_BLK (NBLK + GEMM_NBLK)
#define HS_STRIDE 516

#define LSTM_SMEM ((512*32 + 32*HS_STRIDE + 512*9*2) * 4)   // 100352 B
#define SSTR 136   // smem stride for GEMM planes (bank-bijective frag loads)

// ---------------- device scratch ----------------
__device__ float d_scale[CCH];
__device__ float d_shift[CCH];
__device__ float d_G[2][(size_t)MR * G4];     // 2 x 134 MB
__device__ float d_hbuf[2][2][BB * HHD];
__device__ volatile unsigned g_sense;
__device__ unsigned g_count;
__device__ unsigned g_flag[2][4];             // per (dir, 128-t chunk) tile counters

// ---------------- f32x2 packed helpers ----------------
__device__ __forceinline__ unsigned long long pk2(float x, float y) {
    unsigned long long r;
    asm("mov.b64 %0, {%1, %2};" : "=l"(r) : "f"(x), "f"(y));
    return r;
}
__device__ __forceinline__ void upk2(unsigned long long v, float &x, float &y) {
    asm("mov.b64 {%0, %1}, %2;" : "=f"(x), "=f"(y) : "l"(v));
}
__device__ __forceinline__ void ffma2(unsigned long long &d,
                                      unsigned long long a, unsigned long long b) {
    asm("fma.rn.f32x2 %0, %1, %2, %0;" : "+l"(d) : "l"(a), "l"(b));
}

// ---------------- tf32 helpers ----------------
__device__ __forceinline__ unsigned f2tf32(float f) {
    unsigned r;
    asm("cvt.rna.tf32.f32 %0, %1;" : "=r"(r) : "f"(f));
    return r;
}
__device__ __forceinline__ void split_tf32(float f, float &hi, float &lo) {
    unsigned h = f2tf32(f);
    hi = __uint_as_float(h);
    lo = __uint_as_float(f2tf32(f - hi));
}
__device__ __forceinline__ void mma_tf32(float* d, const unsigned* a, const unsigned* b) {
    asm("mma.sync.aligned.m16n8k8.row.col.f32.tf32.tf32.f32 "
        "{%0,%1,%2,%3}, {%4,%5,%6,%7}, {%8,%9}, {%0,%1,%2,%3};"
        : "+f"(d[0]), "+f"(d[1]), "+f"(d[2]), "+f"(d[3])
        : "r"(a[0]), "r"(a[1]), "r"(a[2]), "r"(a[3]), "r"(b[0]), "r"(b[1]));
}

// ---------------- BN prep ----------------
__global__ void bn_prep_kernel(const float* __restrict__ gamma,
                               const float* __restrict__ beta,
                               const float* __restrict__ mean,
                               const float* __restrict__ var) {
    int c = threadIdx.x;
    float s = gamma[c] * rsqrtf(var[c] + 1e-3f);
    d_scale[c] = s;
    d_shift[c] = beta[c] - mean[c] * s;
}

// ---------------- state + flag init ----------------
__global__ void init_kernel() {
    int i = blockIdx.x * blockDim.x + threadIdx.x;
    if (i < BB * HHD) {
        d_hbuf[0][0][i] = 0.f;
        d_hbuf[1][0][i] = 0.f;
    }
    if (i < 8) ((unsigned*)g_flag)[i] = 0u;
}

// ================= GEMM side of fused kernel =================
__device__ __forceinline__ void gemm_body(float* smem, int g,
                                          const float* __restrict__ x,
                                          const float* __restrict__ Wf,
                                          const float* __restrict__ bf,
                                          const float* __restrict__ Wb,
                                          const float* __restrict__ bb) {
    // priority remap: q-major so dir0 produces chunk q, dir1 produces chunk 3-q
    int q = g >> 10;
    int dir = (g >> 9) & 1;
    int r = g & 511;
    int btile = r >> 4;
    int ctile = r & 15;
    int chunk = dir ? (3 - q) : q;

    const float* Wm = dir ? Wb : Wf;
    const float* bias = dir ? bb : bf;
    float* Out = d_G[dir];

    float* Ah = smem;
    float* Al = Ah + 16 * SSTR;
    float* Bh = Al + 16 * SSTR;
    float* Bl = Bh + 16 * SSTR;

    int tid = threadIdx.x;
    int warp = tid >> 5, lane = tid & 31;
    int gid = lane >> 2, tig = lane & 3;
    int wm = warp >> 2, wn = warp & 3;
    int rowBase = btile * TT + chunk * 128;
    int colBase = ctile * 128;

    int aRow = tid >> 1;
    int aK = (tid & 1) * 8;
    int bK = tid >> 4;
    int bN = (tid & 15) * 8;

    float acc[4][4][4];
    #pragma unroll
    for (int i = 0; i < 4; i++)
        #pragma unroll
        for (int j = 0; j < 4; j++)
            #pragma unroll
            for (int p = 0; p < 4; p++) acc[i][j][p] = 0.f;

    const float* xrow = x + (size_t)(rowBase + aRow) * CCH;
    for (int kt = 0; kt < CCH; kt += 16) {
        // stage A (BN folded) pre-split to hi/lo planes, transposed [k][m]
        {
            float4 v0 = *(const float4*)(xrow + kt + aK);
            float4 v1 = *(const float4*)(xrow + kt + aK + 4);
            float4 sc0 = *(const float4*)(d_scale + kt + aK);
            float4 sc1 = *(const float4*)(d_scale + kt + aK + 4);
            float4 sh0 = *(const float4*)(d_shift + kt + aK);
            float4 sh1 = *(const float4*)(d_shift + kt + aK + 4);
            float va[8] = {fmaf(v0.x, sc0.x, sh0.x), fmaf(v0.y, sc0.y, sh0.y),
                           fmaf(v0.z, sc0.z, sh0.z), fmaf(v0.w, sc0.w, sh0.w),
                           fmaf(v1.x, sc1.x, sh1.x), fmaf(v1.y, sc1.y, sh1.y),
                           fmaf(v1.z, sc1.z, sh1.z), fmaf(v1.w, sc1.w, sh1.w)};
            #pragma unroll
            for (int i = 0; i < 8; i++) {
                float hi, lo;
                split_tf32(va[i], hi, lo);
                Ah[(aK + i) * SSTR + aRow] = hi;
                Al[(aK + i) * SSTR + aRow] = lo;
            }
            const float* wp = Wm + (size_t)(kt + bK) * G4 + colBase + bN;
            float4 w0 = *(const float4*)wp;
            float4 w1 = *(const float4*)(wp + 4);
            float wv[8] = {w0.x, w0.y, w0.z, w0.w, w1.x, w1.y, w1.z, w1.w};
            #pragma unroll
            for (int i = 0; i < 8; i++) {
                float hi, lo;
                split_tf32(wv[i], hi, lo);
                Bh[bK * SSTR + bN + i] = hi;
                Bl[bK * SSTR + bN + i] = lo;
            }
        }
        __syncthreads();

        #pragma unroll
        for (int kf = 0; kf < 16; kf += 8) {
            unsigned ah[4][4], al[4][4];
            #pragma unroll
            for (int mi = 0; mi < 4; mi++) {
                int m = wm * 64 + mi * 16 + gid;
                int o0 = (kf + tig) * SSTR + m;
                int o1 = (kf + tig + 4) * SSTR + m;
                ah[mi][0] = __float_as_uint(Ah[o0]);
                ah[mi][1] = __float_as_uint(Ah[o0 + 8]);
                ah[mi][2] = __float_as_uint(Ah[o1]);
                ah[mi][3] = __float_as_uint(Ah[o1 + 8]);
                al[mi][0] = __float_as_uint(Al[o0]);
                al[mi][1] = __float_as_uint(Al[o0 + 8]);
                al[mi][2] = __float_as_uint(Al[o1]);
                al[mi][3] = __float_as_uint(Al[o1 + 8]);
            }
            #pragma unroll
            for (int ni = 0; ni < 4; ni++) {
                int n = wn * 32 + ni * 8 + gid;
                int p0 = (kf + tig) * SSTR + n;
                int p1 = (kf + tig + 4) * SSTR + n;
                unsigned bh[2], bl[2];
                bh[0] = __float_as_uint(Bh[p0]);
                bh[1] = __float_as_uint(Bh[p1]);
                bl[0] = __float_as_uint(Bl[p0]);
                bl[1] = __float_as_uint(Bl[p1]);
                #pragma unroll
                for (int mi = 0; mi < 4; mi++) {
                    mma_tf32(acc[mi][ni], ah[mi], bh);
                    mma_tf32(acc[mi][ni], ah[mi], bl);
                    mma_tf32(acc[mi][ni], al[mi], bh);
                }
            }
        }
        __syncthreads();
    }

    #pragma unroll
    for (int mi = 0; mi < 4; mi++) {
        int row0 = rowBase + wm * 64 + mi * 16 + gid;
        #pragma unroll
        for (int ni = 0; ni < 4; ni++) {
            int col = colBase + wn * 32 + ni * 8 + tig * 2;
            float b0 = bias[col], b1 = bias[col + 1];
            float2 v0 = make_float2(acc[mi][ni][0] + b0, acc[mi][ni][1] + b1);
            float2 v1 = make_float2(acc[mi][ni][2] + b0, acc[mi][ni][3] + b1);
            *(float2*)(Out + (size_t)row0 * G4 + col) = v0;
            *(float2*)(Out + (size_t)(row0 + 8) * G4 + col) = v1;
        }
    }

    __threadfence();
    __syncthreads();
    if (tid == 0) atomicAdd(&g_flag[dir][chunk], 1u);
}

// ================= recurrence side of fused kernel =================
__device__ __forceinline__ void lstm_body(float* smem,
                                          const float* __restrict__ Uf,
                                          const float* __restrict__ Ub) {
    float* us   = smem;                       // [512][32]
    float* hs   = smem + 512 * 32;            // [32][HS_STRIDE]
    float* redf = hs + 32 * HS_STRIDE;        // [512][9][2]

    int tid = threadIdx.x;
    int dir = blockIdx.x >> 6;
    int blk = blockIdx.x & 63;
    int u0 = blk * UPB;
    const float* U = dir ? Ub : Uf;
    const float* Gp = d_G[dir];

    for (int i = tid; i < 512 * 32; i += 256) {
        int k = i >> 5, j = i & 31;
        us[i] = U[(size_t)k * G4 + (j >> 3) * HHD + u0 + (j & 7)];
    }

    int w = tid >> 5, lane = tid & 31;
    int rg = lane & 7;
    int cg = lane >> 3;
    int k0 = w * 64;
    int eb = tid >> 3, eu = tid & 7;

    float c = 0.f;
    unsigned sense_local = 0;
    __syncthreads();

    for (int t = 0; t < TT; t++) {
        int tt = dir ? (TT - 1 - t) : t;
        int rb = t & 1;
        const float* hg = d_hbuf[dir][rb];

        // wait until this t-chunk of G has been produced by the GEMM blocks
        {
            int chunk = tt >> 7;
            if (tid == 0) {
                volatile unsigned* fl = &g_flag[dir][chunk];
                while (*fl < 512u) { }
            }
            __syncthreads();
        }

        float gz[4];
        {
            const float* gp = Gp + (size_t)(eb * TT + tt) * G4 + u0 + eu;
            gz[0] = __ldcg(gp);
            gz[1] = __ldcg(gp + 512);
            gz[2] = __ldcg(gp + 1024);
            gz[3] = __ldcg(gp + 1536);
        }

        #pragma unroll
        for (int i = 0; i < 16; i++) {
            int idx = lane + 32 * i;
            int b = idx >> 4, qq = idx & 15;
            float4 v = __ldcg((const float4*)(hg + b * HHD + k0 + qq * 4));
            *(float4*)&hs[b * HS_STRIDE + k0 + qq * 4] = v;
        }
        __syncwarp();

        unsigned long long acc[4][4];
        #pragma unroll
        for (int i = 0; i < 4; i++)
            #pragma unroll
            for (int j = 0; j < 4; j++) acc[i][j] = 0ull;

        #pragma unroll 4
        for (int k = k0; k < k0 + 64; k++) {
            float a0 = hs[(rg     ) * HS_STRIDE + k];
            float a1 = hs[(rg +  8) * HS_STRIDE + k];
            float a2 = hs[(rg + 16) * HS_STRIDE + k];
            float a3 = hs[(rg + 24) * HS_STRIDE + k];
            ulonglong2 bA = *(const ulonglong2*)&us[k * 32 + cg * 8];
            ulonglong2 bB = *(const ulonglong2*)&us[k * 32 + cg * 8 + 4];
            unsigned long long ap0 = pk2(a0, a0), ap1 = pk2(a1, a1);
            unsigned long long ap2 = pk2(a2, a2), ap3 = pk2(a3, a3);
            ffma2(acc[0][0], ap0, bA.x); ffma2(acc[0][1], ap0, bA.y);
            ffma2(acc[0][2], ap0, bB.x); ffma2(acc[0][3], ap0, bB.y);
            ffma2(acc[1][0], ap1, bA.x); ffma2(acc[1][1], ap1, bA.y);
            ffma2(acc[1][2], ap1, bB.x); ffma2(acc[1][3], ap1, bB.y);
            ffma2(acc[2][0], ap2, bA.x); ffma2(acc[2][1], ap2, bA.y);
            ffma2(acc[2][2], ap2, bB.x); ffma2(acc[2][3], ap2, bB.y);
            ffma2(acc[3][0], ap3, bA.x); ffma2(acc[3][1], ap3, bA.y);
            ffma2(acc[3][2], ap3, bB.x); ffma2(acc[3][3], ap3, bB.y);
        }

        #pragma unroll
        for (int i = 0; i < 4; i++) {
            int row = rg + 8 * i;
            #pragma unroll
            for (int j = 0; j < 4; j++) {
                int col2 = cg * 4 + j;
                float xx, yy;
                upk2(acc[i][j], xx, yy);
                *(float2*)&redf[(((col2 << 5) | row) * 9 + w) * 2] = make_float2(xx, yy);
            }
        }
        __syncthreads();

        {
            float z[4];
            #pragma unroll
            for (int g = 0; g < 4; g++) {
                int col = g * 8 + eu;
                int base = (((col >> 1) * 32 + eb) * 9) * 2 + (col & 1);
                float s = gz[g];
                #pragma unroll
                for (int sw = 0; sw < 8; sw++) s += redf[base + sw * 2];
                z[g] = s;
            }
            float ig = 1.f / (1.f + __expf(-z[0]));
            float fg = 1.f / (1.f + __expf(-z[1]));
            float gv = tanhf(z[2]);
            float og = 1.f / (1.f + __expf(-z[3]));
            c = fg * c + ig * gv;
            d_hbuf[dir][rb ^ 1][eb * HHD + u0 + eu] = og * tanhf(c);
        }

        __syncthreads();
        if (tid == 0) {
            sense_local ^= 1u;
            __threadfence();
            if (atomicAdd(&g_count, 1u) == NBLK - 1) {
                g_count = 0u;
                __threadfence();
                *(volatile unsigned*)&g_sense = sense_local;
            } else {
                while (*(volatile unsigned*)&g_sense != sense_local) { }
            }
            __threadfence();
        }
        __syncthreads();
    }
}

// ================= fused kernel =================
__global__ __launch_bounds__(256, 2) void fused_kernel(const float* __restrict__ x,
                                                       const float* __restrict__ Wf,
                                                       const float* __restrict__ bf,
                                                       const float* __restrict__ Wb,
                                                       const float* __restrict__ bb,
                                                       const float* __restrict__ Uf,
                                                       const float* __restrict__ Ub) {
    extern __shared__ float smem[];
    if (blockIdx.x < NBLK) {
        lstm_body(smem, Uf, Ub);
    } else {
        gemm_body(smem, blockIdx.x - NBLK, x, Wf, bf, Wb, bb);
    }
}

// ---------------- final concat ----------------
__global__ void final_kernel(float* __restrict__ out) {
    int i = blockIdx.x * blockDim.x + threadIdx.x;
    if (i < BB * 2 * HHD) {
        int b = i >> 10;
        int j = i & 1023;
        out[i] = (j < HHD) ? d_hbuf[0][0][b * HHD + j]
                           : d_hbuf[1][0][b * HHD + j - HHD];
    }
}

// ---------------- launch ----------------
extern "C" void kernel_launch(void* const* d_in, const int* in_sizes, int n_in,
                              void* d_out, int out_size) {
    const float* x     = (const float*)d_in[0];
    const float* gamma = (const float*)d_in[1];
    const float* beta  = (const float*)d_in[2];
    const float* mean  = (const float*)d_in[3];
    const float* var   = (const float*)d_in[4];
    const float* Wf    = (const float*)d_in[5];
    const float* Uf    = (const float*)d_in[6];
    const float* bf    = (const float*)d_in[7];
    const float* Wb    = (const float*)d_in[8];
    const float* Ub    = (const float*)d_in[9];
    const float* bb    = (const float*)d_in[10];
    float* out = (float*)d_out;

    cudaFuncSetAttribute(fused_kernel, cudaFuncAttributeMaxDynamicSharedMemorySize,
                         LSTM_SMEM);

    bn_prep_kernel<<<1, 512>>>(gamma, beta, mean, var);
    init_kernel<<<64, 256>>>();

    fused_kernel<<<TOTAL_BLK, 256, LSTM_SMEM>>>(x, Wf, bf, Wb, bb, Uf, Ub);

    final_kernel<<<128, 256>>>(out);
}

// round 5
// speedup vs baseline: 2.4860x; 2.4860x over previous
#include <cuda_runtime.h>
#include <cuda_bf16.h>
#include <math.h>

#define BB 32
#define TT 512
#define CCH 512
#define HHD 512
#define G4 2048
#define MR (BB*TT)   // 16384

#define UPB 8          // hidden units per persistent block
#define NBLK 128       // persistent grid (64 per direction)
#define HS_STRIDE 516  // padded stride for h in smem

#define LSTM_SMEM ((512*32 + 32*HS_STRIDE + 512*9*2) * 4)

// ---------------- device scratch ----------------
__device__ float d_scale[CCH];
__device__ float d_shift[CCH];
__device__ float d_G[2][(size_t)MR * G4];     // 2 x 134 MB
__device__ float d_hbuf[2][2][BB * HHD];
__device__ volatile unsigned g_sense;
__device__ unsigned g_count;

// ---------------- f32x2 packed helpers (recurrence) ----------------
__device__ __forceinline__ unsigned long long pk2(float x, float y) {
    unsigned long long r;
    asm("mov.b64 %0, {%1, %2};" : "=l"(r) : "f"(x), "f"(y));
    return r;
}
__device__ __forceinline__ void upk2(unsigned long long v, float &x, float &y) {
    asm("mov.b64 {%0, %1}, %2;" : "=f"(x), "=f"(y) : "l"(v));
}
__device__ __forceinline__ void ffma2(unsigned long long &d,
                                      unsigned long long a, unsigned long long b) {
    asm("fma.rn.f32x2 %0, %1, %2, %0;" : "+l"(d) : "l"(a), "l"(b));
}

// ---------------- bf16 split helpers ----------------
__device__ __forceinline__ void split_bf16(float f, unsigned short &hi, unsigned short &lo) {
    __nv_bfloat16 h = __float2bfloat16(f);
    float hf = __bfloat162float(h);
    __nv_bfloat16 l = __float2bfloat16(f - hf);
    hi = __bfloat16_as_ushort(h);
    lo = __bfloat16_as_ushort(l);
}
__device__ __forceinline__ unsigned pk16(unsigned short a, unsigned short b) {
    return (unsigned)a | ((unsigned)b << 16);
}
__device__ __forceinline__ void mma_bf16(float* d, const unsigned* a, const unsigned* b) {
    asm("mma.sync.aligned.m16n8k16.row.col.f32.bf16.bf16.f32 "
        "{%0,%1,%2,%3}, {%4,%5,%6,%7}, {%8,%9}, {%0,%1,%2,%3};"
        : "+f"(d[0]), "+f"(d[1]), "+f"(d[2]), "+f"(d[3])
        : "r"(a[0]), "r"(a[1]), "r"(a[2]), "r"(a[3]), "r"(b[0]), "r"(b[1]));
}

// ---------------- BN prep ----------------
__global__ void bn_prep_kernel(const float* __restrict__ gamma,
                               const float* __restrict__ beta,
                               const float* __restrict__ mean,
                               const float* __restrict__ var) {
    int c = threadIdx.x;
    float s = gamma[c] * rsqrtf(var[c] + 1e-3f);
    d_scale[c] = s;
    d_shift[c] = beta[c] - mean[c] * s;
}

// ---------------- big GEMM: G = BN(x)@W + b via 3-split bf16 mma ----------------
// block 128x128, BK=16, 8 warps as 2(m) x 4(n), warp tile 64x32
// smem planes hold k-pair-packed bf16x2 words: plane[kp][col], kp = k/2 in 0..7
#define SSTR2 136   // uint32 stride: (136 mod 32)=8 -> frag loads bank-bijective

__global__ __launch_bounds__(256, 2) void gemm_tc_kernel(const float* __restrict__ x,
                                                         const float* __restrict__ Wf,
                                                         const float* __restrict__ bf,
                                                         const float* __restrict__ Wb,
                                                         const float* __restrict__ bb) {
    __shared__ unsigned Ah[8 * SSTR2], Al[8 * SSTR2];
    __shared__ unsigned Bh[8 * SSTR2], Bl[8 * SSTR2];

    int dir = blockIdx.z;
    const float* Wm = dir ? Wb : Wf;
    const float* bias = dir ? bb : bf;
    float* Out = d_G[dir];

    int tid = threadIdx.x;
    int warp = tid >> 5, lane = tid & 31;
    int gid = lane >> 2, tig = lane & 3;
    int wm = warp >> 2, wn = warp & 3;          // 2 x 4 warps
    int rowBase = blockIdx.y * 128;
    int colBase = blockIdx.x * 128;

    // staging roles
    int aRow = tid >> 1;                 // 0..127
    int aK = (tid & 1) * 8;              // k offset 0 or 8
    int bKp = tid >> 5;                  // k-pair 0..7
    int bN = (tid & 31) * 4;             // 0..124

    float acc[4][4][4];                  // [mi][ni][frag]
    #pragma unroll
    for (int i = 0; i < 4; i++)
        #pragma unroll
        for (int j = 0; j < 4; j++)
            #pragma unroll
            for (int q = 0; q < 4; q++) acc[i][j][q] = 0.f;

    const float* xrow = x + (size_t)(rowBase + aRow) * CCH;
    for (int kt = 0; kt < CCH; kt += 16) {
        // ---- stage A (BN folded), split hi/lo, pack k-pairs ----
        {
            float4 v0 = *(const float4*)(xrow + kt + aK);
            float4 v1 = *(const float4*)(xrow + kt + aK + 4);
            float4 sc0 = *(const float4*)(d_scale + kt + aK);
            float4 sc1 = *(const float4*)(d_scale + kt + aK + 4);
            float4 sh0 = *(const float4*)(d_shift + kt + aK);
            float4 sh1 = *(const float4*)(d_shift + kt + aK + 4);
            float va[8] = {fmaf(v0.x, sc0.x, sh0.x), fmaf(v0.y, sc0.y, sh0.y),
                           fmaf(v0.z, sc0.z, sh0.z), fmaf(v0.w, sc0.w, sh0.w),
                           fmaf(v1.x, sc1.x, sh1.x), fmaf(v1.y, sc1.y, sh1.y),
                           fmaf(v1.z, sc1.z, sh1.z), fmaf(v1.w, sc1.w, sh1.w)};
            unsigned short h[8], l[8];
            #pragma unroll
            for (int i = 0; i < 8; i++) split_bf16(va[i], h[i], l[i]);
            #pragma unroll
            for (int p = 0; p < 4; p++) {
                int kp = (aK >> 1) + p;
                Ah[kp * SSTR2 + aRow] = pk16(h[2 * p], h[2 * p + 1]);
                Al[kp * SSTR2 + aRow] = pk16(l[2 * p], l[2 * p + 1]);
            }
        }
        // ---- stage B: 2 k-rows x 4 n per thread ----
        {
            const float* wp0 = Wm + (size_t)(kt + 2 * bKp) * G4 + colBase + bN;
            const float* wp1 = wp0 + G4;
            float4 w0 = *(const float4*)wp0;   // k even
            float4 w1 = *(const float4*)wp1;   // k odd
            float e[4] = {w0.x, w0.y, w0.z, w0.w};
            float o[4] = {w1.x, w1.y, w1.z, w1.w};
            #pragma unroll
            for (int i = 0; i < 4; i++) {
                unsigned short he, le, ho, lo;
                split_bf16(e[i], he, le);
                split_bf16(o[i], ho, lo);
                Bh[bKp * SSTR2 + bN + i] = pk16(he, ho);
                Bl[bKp * SSTR2 + bN + i] = pk16(le, lo);
            }
        }
        __syncthreads();

        // ---- one K=16 mma group ----
        {
            unsigned ah[4][4], al[4][4];
            #pragma unroll
            for (int mi = 0; mi < 4; mi++) {
                int m = wm * 64 + mi * 16 + gid;
                int o0 = tig * SSTR2 + m;
                int o1 = (tig + 4) * SSTR2 + m;
                ah[mi][0] = Ah[o0];
                ah[mi][1] = Ah[o0 + 8];
                ah[mi][2] = Ah[o1];
                ah[mi][3] = Ah[o1 + 8];
                al[mi][0] = Al[o0];
                al[mi][1] = Al[o0 + 8];
                al[mi][2] = Al[o1];
                al[mi][3] = Al[o1 + 8];
            }
            #pragma unroll
            for (int ni = 0; ni < 4; ni++) {
                int n = wn * 32 + ni * 8 + gid;
                unsigned bh[2], bl[2];
                bh[0] = Bh[tig * SSTR2 + n];
                bh[1] = Bh[(tig + 4) * SSTR2 + n];
                bl[0] = Bl[tig * SSTR2 + n];
                bl[1] = Bl[(tig + 4) * SSTR2 + n];
                #pragma unroll
                for (int mi = 0; mi < 4; mi++) {
                    mma_bf16(acc[mi][ni], ah[mi], bh);
                    mma_bf16(acc[mi][ni], ah[mi], bl);
                    mma_bf16(acc[mi][ni], al[mi], bh);
                }
            }
        }
        __syncthreads();
    }

    // epilogue: + bias, store
    #pragma unroll
    for (int mi = 0; mi < 4; mi++) {
        int row0 = rowBase + wm * 64 + mi * 16 + gid;
        #pragma unroll
        for (int ni = 0; ni < 4; ni++) {
            int col = colBase + wn * 32 + ni * 8 + tig * 2;
            float b0 = bias[col], b1 = bias[col + 1];
            float2 v0 = make_float2(acc[mi][ni][0] + b0, acc[mi][ni][1] + b1);
            float2 v1 = make_float2(acc[mi][ni][2] + b0, acc[mi][ni][3] + b1);
            *(float2*)(Out + (size_t)row0 * G4 + col) = v0;
            *(float2*)(Out + (size_t)(row0 + 8) * G4 + col) = v1;
        }
    }
}

// ---------------- state init ----------------
__global__ void init_kernel() {
    int i = blockIdx.x * blockDim.x + threadIdx.x;
    if (i < BB * HHD) {
        d_hbuf[0][0][i] = 0.f;
        d_hbuf[1][0][i] = 0.f;
    }
}

// ---------------- persistent bidirectional LSTM recurrence ----------------
__global__ __launch_bounds__(256, 1) void lstm_persist(const float* __restrict__ Uf,
                                                       const float* __restrict__ Ub) {
    extern __shared__ float smem[];
    float* us   = smem;                       // [512][32]
    float* hs   = smem + 512 * 32;            // [32][HS_STRIDE]
    float* redf = hs + 32 * HS_STRIDE;        // [512][9][2]

    int tid = threadIdx.x;
    int dir = blockIdx.x >> 6;
    int blk = blockIdx.x & 63;
    int u0 = blk * UPB;
    const float* U = dir ? Ub : Uf;
    const float* Gp = d_G[dir];

    for (int i = tid; i < 512 * 32; i += 256) {
        int k = i >> 5, j = i & 31;
        us[i] = U[(size_t)k * G4 + (j >> 3) * HHD + u0 + (j & 7)];
    }

    int w = tid >> 5, lane = tid & 31;
    int rg = lane & 7;
    int cg = lane >> 3;
    int k0 = w * 64;
    int eb = tid >> 3, eu = tid & 7;

    float c = 0.f;
    unsigned sense_local = 0;
    __syncthreads();

    for (int t = 0; t < TT; t++) {
        int tt = dir ? (TT - 1 - t) : t;
        int rb = t & 1;
        const float* hg = d_hbuf[dir][rb];

        float gz[4];
        {
            const float* gp = Gp + (size_t)(eb * TT + tt) * G4 + u0 + eu;
            gz[0] = __ldg(gp);
            gz[1] = __ldg(gp + 512);
            gz[2] = __ldg(gp + 1024);
            gz[3] = __ldg(gp + 1536);
        }

        #pragma unroll
        for (int i = 0; i < 16; i++) {
            int idx = lane + 32 * i;
            int b = idx >> 4, q = idx & 15;
            float4 v = __ldcg((const float4*)(hg + b * HHD + k0 + q * 4));
            *(float4*)&hs[b * HS_STRIDE + k0 + q * 4] = v;
        }
        __syncwarp();

        unsigned long long acc[4][4];
        #pragma unroll
        for (int i = 0; i < 4; i++)
            #pragma unroll
            for (int j = 0; j < 4; j++) acc[i][j] = 0ull;

        #pragma unroll 4
        for (int k = k0; k < k0 + 64; k++) {
            float a0 = hs[(rg     ) * HS_STRIDE + k];
            float a1 = hs[(rg +  8) * HS_STRIDE + k];
            float a2 = hs[(rg + 16) * HS_STRIDE + k];
            float a3 = hs[(rg + 24) * HS_STRIDE + k];
            ulonglong2 bA = *(const ulonglong2*)&us[k * 32 + cg * 8];
            ulonglong2 bB = *(const ulonglong2*)&us[k * 32 + cg * 8 + 4];
            unsigned long long ap0 = pk2(a0, a0), ap1 = pk2(a1, a1);
            unsigned long long ap2 = pk2(a2, a2), ap3 = pk2(a3, a3);
            ffma2(acc[0][0], ap0, bA.x); ffma2(acc[0][1], ap0, bA.y);
            ffma2(acc[0][2], ap0, bB.x); ffma2(acc[0][3], ap0, bB.y);
            ffma2(acc[1][0], ap1, bA.x); ffma2(acc[1][1], ap1, bA.y);
            ffma2(acc[1][2], ap1, bB.x); ffma2(acc[1][3], ap1, bB.y);
            ffma2(acc[2][0], ap2, bA.x); ffma2(acc[2][1], ap2, bA.y);
            ffma2(acc[2][2], ap2, bB.x); ffma2(acc[2][3], ap2, bB.y);
            ffma2(acc[3][0], ap3, bA.x); ffma2(acc[3][1], ap3, bA.y);
            ffma2(acc[3][2], ap3, bB.x); ffma2(acc[3][3], ap3, bB.y);
        }

        #pragma unroll
        for (int i = 0; i < 4; i++) {
            int row = rg + 8 * i;
            #pragma unroll
            for (int j = 0; j < 4; j++) {
                int col2 = cg * 4 + j;
                float xx, yy;
                upk2(acc[i][j], xx, yy);
                *(float2*)&redf[(((col2 << 5) | row) * 9 + w) * 2] = make_float2(xx, yy);
            }
        }
        __syncthreads();

        {
            float z[4];
            #pragma unroll
            for (int g = 0; g < 4; g++) {
                int col = g * 8 + eu;
                int base = (((col >> 1) * 32 + eb) * 9) * 2 + (col & 1);
                float s = gz[g];
                #pragma unroll
                for (int sw = 0; sw < 8; sw++) s += redf[base + sw * 2];
                z[g] = s;
            }
            float ig = 1.f / (1.f + __expf(-z[0]));
            float fg = 1.f / (1.f + __expf(-z[1]));
            float gv = tanhf(z[2]);
            float og = 1.f / (1.f + __expf(-z[3]));
            c = fg * c + ig * gv;
            d_hbuf[dir][rb ^ 1][eb * HHD + u0 + eu] = og * tanhf(c);
        }

        __syncthreads();
        if (tid == 0) {
            sense_local ^= 1u;
            __threadfence();
            if (atomicAdd(&g_count, 1u) == NBLK - 1) {
                g_count = 0u;
                __threadfence();
                *(volatile unsigned*)&g_sense = sense_local;
            } else {
                while (*(volatile unsigned*)&g_sense != sense_local) { }
            }
            __threadfence();
        }
        __syncthreads();
    }
}

// ---------------- final concat ----------------
__global__ void final_kernel(float* __restrict__ out) {
    int i = blockIdx.x * blockDim.x + threadIdx.x;
    if (i < BB * 2 * HHD) {
        int b = i >> 10;
        int j = i & 1023;
        out[i] = (j < HHD) ? d_hbuf[0][0][b * HHD + j]
                           : d_hbuf[1][0][b * HHD + j - HHD];
    }
}

// ---------------- launch ----------------
extern "C" void kernel_launch(void* const* d_in, const int* in_sizes, int n_in,
                              void* d_out, int out_size) {
    const float* x     = (const float*)d_in[0];
    const float* gamma = (const float*)d_in[1];
    const float* beta  = (const float*)d_in[2];
    const float* mean  = (const float*)d_in[3];
    const float* var   = (const float*)d_in[4];
    const float* Wf    = (const float*)d_in[5];
    const float* Uf    = (const float*)d_in[6];
    const float* bf    = (const float*)d_in[7];
    const float* Wb    = (const float*)d_in[8];
    const float* Ub    = (const float*)d_in[9];
    const float* bb    = (const float*)d_in[10];
    float* out = (float*)d_out;

    cudaFuncSetAttribute(lstm_persist, cudaFuncAttributeMaxDynamicSharedMemorySize,
                         LSTM_SMEM);

    bn_prep_kernel<<<1, 512>>>(gamma, beta, mean, var);

    dim3 ggrid(G4 / 128, MR / 128, 2);
    gemm_tc_kernel<<<ggrid, 256>>>(x, Wf, bf, Wb, bb);

    init_kernel<<<64, 256>>>();

    lstm_persist<<<NBLK, 256, LSTM_SMEM>>>(Uf, Ub);

    final_kernel<<<128, 256>>>(out);
}

// round 6
// speedup vs baseline: 3.0356x; 1.2211x over previous
#include <cuda_runtime.h>
#include <cuda_bf16.h>
#include <math.h>

#define BB 32
#define TT 512
#define CCH 512
#define HHD 512
#define G4 2048
#define MR (BB*TT)   // 16384

#define UPB 8          // hidden units per persistent block
#define NBLK 128       // persistent grid (64 per direction)
#define DBLK 64        // blocks per direction

// ---- persistent-kernel smem layout (uint/float words) ----
#define US_H_OFF 0          // [256 kp][40] packed U hi
#define US_L_OFF 10240      // [256 kp][40] packed U lo
#define HS_H_OFF 20480      // 8 warp slices x [32 kp][40] packed h hi (red overlay)
#define HS_L_OFF 30720      // 8 warp slices x [32 kp][40] packed h lo
#define LSTM_WORDS 40960
#define LSTM_SMEM (LSTM_WORDS * 4)   // 163840 B

// ---------------- device scratch ----------------
__device__ float d_scale[CCH];
__device__ float d_shift[CCH];
__device__ float d_G[2][(size_t)MR * G4];     // 2 x 134 MB
__device__ unsigned d_hpk[2][2][2][256 * 32]; // [dir][pingpong][hi/lo][kp*32+b]
__device__ float d_hout[2][BB * HHD];         // final fp32 h per direction
__device__ volatile unsigned g_sense[2];
__device__ unsigned g_count[2];

// ---------------- bf16 split helpers ----------------
__device__ __forceinline__ void split_bf16(float f, unsigned short &hi, unsigned short &lo) {
    __nv_bfloat16 h = __float2bfloat16(f);
    float hf = __bfloat162float(h);
    __nv_bfloat16 l = __float2bfloat16(f - hf);
    hi = __bfloat16_as_ushort(h);
    lo = __bfloat16_as_ushort(l);
}
__device__ __forceinline__ unsigned pk16(unsigned short a, unsigned short b) {
    return (unsigned)a | ((unsigned)b << 16);
}
__device__ __forceinline__ void mma_bf16(float* d, const unsigned* a, const unsigned* b) {
    asm("mma.sync.aligned.m16n8k16.row.col.f32.bf16.bf16.f32 "
        "{%0,%1,%2,%3}, {%4,%5,%6,%7}, {%8,%9}, {%0,%1,%2,%3};"
        : "+f"(d[0]), "+f"(d[1]), "+f"(d[2]), "+f"(d[3])
        : "r"(a[0]), "r"(a[1]), "r"(a[2]), "r"(a[3]), "r"(b[0]), "r"(b[1]));
}

// ---------------- BN prep ----------------
__global__ void bn_prep_kernel(const float* __restrict__ gamma,
                               const float* __restrict__ beta,
                               const float* __restrict__ mean,
                               const float* __restrict__ var) {
    int c = threadIdx.x;
    float s = gamma[c] * rsqrtf(var[c] + 1e-3f);
    d_scale[c] = s;
    d_shift[c] = beta[c] - mean[c] * s;
}

// ---------------- big GEMM: G = BN(x)@W + b via 3-split bf16 mma ----------------
#define SSTR2 136

__global__ __launch_bounds__(256, 2) void gemm_tc_kernel(const float* __restrict__ x,
                                                         const float* __restrict__ Wf,
                                                         const float* __restrict__ bf,
                                                         const float* __restrict__ Wb,
                                                         const float* __restrict__ bb) {
    __shared__ unsigned Ah[8 * SSTR2], Al[8 * SSTR2];
    __shared__ unsigned Bh[8 * SSTR2], Bl[8 * SSTR2];

    int dir = blockIdx.z;
    const float* Wm = dir ? Wb : Wf;
    const float* bias = dir ? bb : bf;
    float* Out = d_G[dir];

    int tid = threadIdx.x;
    int warp = tid >> 5, lane = tid & 31;
    int gid = lane >> 2, tig = lane & 3;
    int wm = warp >> 2, wn = warp & 3;
    int rowBase = blockIdx.y * 128;
    int colBase = blockIdx.x * 128;

    int aRow = tid >> 1;
    int aK = (tid & 1) * 8;
    int bKp = tid >> 5;
    int bN = (tid & 31) * 4;

    float acc[4][4][4];
    #pragma unroll
    for (int i = 0; i < 4; i++)
        #pragma unroll
        for (int j = 0; j < 4; j++)
            #pragma unroll
            for (int q = 0; q < 4; q++) acc[i][j][q] = 0.f;

    const float* xrow = x + (size_t)(rowBase + aRow) * CCH;
    for (int kt = 0; kt < CCH; kt += 16) {
        {
            float4 v0 = *(const float4*)(xrow + kt + aK);
            float4 v1 = *(const float4*)(xrow + kt + aK + 4);
            float4 sc0 = *(const float4*)(d_scale + kt + aK);
            float4 sc1 = *(const float4*)(d_scale + kt + aK + 4);
            float4 sh0 = *(const float4*)(d_shift + kt + aK);
            float4 sh1 = *(const float4*)(d_shift + kt + aK + 4);
            float va[8] = {fmaf(v0.x, sc0.x, sh0.x), fmaf(v0.y, sc0.y, sh0.y),
                           fmaf(v0.z, sc0.z, sh0.z), fmaf(v0.w, sc0.w, sh0.w),
                           fmaf(v1.x, sc1.x, sh1.x), fmaf(v1.y, sc1.y, sh1.y),
                           fmaf(v1.z, sc1.z, sh1.z), fmaf(v1.w, sc1.w, sh1.w)};
            unsigned short h[8], l[8];
            #pragma unroll
            for (int i = 0; i < 8; i++) split_bf16(va[i], h[i], l[i]);
            #pragma unroll
            for (int p = 0; p < 4; p++) {
                int kp = (aK >> 1) + p;
                Ah[kp * SSTR2 + aRow] = pk16(h[2 * p], h[2 * p + 1]);
                Al[kp * SSTR2 + aRow] = pk16(l[2 * p], l[2 * p + 1]);
            }
        }
        {
            const float* wp0 = Wm + (size_t)(kt + 2 * bKp) * G4 + colBase + bN;
            const float* wp1 = wp0 + G4;
            float4 w0 = *(const float4*)wp0;
            float4 w1 = *(const float4*)wp1;
            float e[4] = {w0.x, w0.y, w0.z, w0.w};
            float o[4] = {w1.x, w1.y, w1.z, w1.w};
            #pragma unroll
            for (int i = 0; i < 4; i++) {
                unsigned short he, le, ho, lo;
                split_bf16(e[i], he, le);
                split_bf16(o[i], ho, lo);
                Bh[bKp * SSTR2 + bN + i] = pk16(he, ho);
                Bl[bKp * SSTR2 + bN + i] = pk16(le, lo);
            }
        }
        __syncthreads();

        {
            unsigned ah[4][4], al[4][4];
            #pragma unroll
            for (int mi = 0; mi < 4; mi++) {
                int m = wm * 64 + mi * 16 + gid;
                int o0 = tig * SSTR2 + m;
                int o1 = (tig + 4) * SSTR2 + m;
                ah[mi][0] = Ah[o0];
                ah[mi][1] = Ah[o0 + 8];
                ah[mi][2] = Ah[o1];
                ah[mi][3] = Ah[o1 + 8];
                al[mi][0] = Al[o0];
                al[mi][1] = Al[o0 + 8];
                al[mi][2] = Al[o1];
                al[mi][3] = Al[o1 + 8];
            }
            #pragma unroll
            for (int ni = 0; ni < 4; ni++) {
                int n = wn * 32 + ni * 8 + gid;
                unsigned bh[2], bl[2];
                bh[0] = Bh[tig * SSTR2 + n];
                bh[1] = Bh[(tig + 4) * SSTR2 + n];
                bl[0] = Bl[tig * SSTR2 + n];
                bl[1] = Bl[(tig + 4) * SSTR2 + n];
                #pragma unroll
                for (int mi = 0; mi < 4; mi++) {
                    mma_bf16(acc[mi][ni], ah[mi], bh);
                    mma_bf16(acc[mi][ni], ah[mi], bl);
                    mma_bf16(acc[mi][ni], al[mi], bh);
                }
            }
        }
        __syncthreads();
    }

    #pragma unroll
    for (int mi = 0; mi < 4; mi++) {
        int row0 = rowBase + wm * 64 + mi * 16 + gid;
        #pragma unroll
        for (int ni = 0; ni < 4; ni++) {
            int col = colBase + wn * 32 + ni * 8 + tig * 2;
            float b0 = bias[col], b1 = bias[col + 1];
            float2 v0 = make_float2(acc[mi][ni][0] + b0, acc[mi][ni][1] + b1);
            float2 v1 = make_float2(acc[mi][ni][2] + b0, acc[mi][ni][3] + b1);
            *(float2*)(Out + (size_t)row0 * G4 + col) = v0;
            *(float2*)(Out + (size_t)(row0 + 8) * G4 + col) = v1;
        }
    }
}

// ---------------- state init (zero packed h, every launch) ----------------
__global__ void init_kernel() {
    int i = blockIdx.x * blockDim.x + threadIdx.x;
    unsigned* p = &d_hpk[0][0][0][0];
    int total = 2 * 2 * 2 * 256 * 32;      // 65536 words
    for (int j = i; j < total; j += gridDim.x * blockDim.x) p[j] = 0u;
}

// ---------------- persistent bidirectional LSTM recurrence (tensor-core) ----------------
__global__ __launch_bounds__(256, 1) void lstm_persist(const float* __restrict__ Uf,
                                                       const float* __restrict__ Ub) {
    extern __shared__ unsigned smem[];
    unsigned* usH = smem + US_H_OFF;      // [256][40]
    unsigned* usL = smem + US_L_OFF;
    unsigned* hsH = smem + HS_H_OFF;      // 8 x [32][40]
    unsigned* hsL = smem + HS_L_OFF;

    int tid = threadIdx.x;
    int dir = blockIdx.x >> 6;
    int blk = blockIdx.x & 63;
    int u0 = blk * UPB;
    const float* U = dir ? Ub : Uf;
    const float* Gp = d_G[dir];

    // ---- stage + split this block's 32 U columns once ----
    for (int i = tid; i < 256 * 32; i += 256) {
        int kp = i >> 5, j = i & 31;
        const float* up = U + (size_t)(2 * kp) * G4 + (j >> 3) * HHD + u0 + (j & 7);
        float e = up[0];
        float o = up[G4];
        unsigned short he, le, ho, lo;
        split_bf16(e, he, le);
        split_bf16(o, ho, lo);
        usH[kp * 40 + j] = pk16(he, ho);
        usL[kp * 40 + j] = pk16(le, lo);
    }

    int w = tid >> 5, lane = tid & 31;
    int gid = lane >> 2, tig = lane & 3;
    int eb = tid >> 3, eu = tid & 7;      // epilogue role
    int kp0 = w * 32;                     // this warp's global kp base

    unsigned* myHsH = hsH + w * 1280;     // [32 kp][40]
    unsigned* myHsL = hsL + w * 1280;

    float c = 0.f;
    unsigned sense_local = 0;
    __syncthreads();

    for (int t = 0; t < TT; t++) {
        int tt = dir ? (TT - 1 - t) : t;
        int rb = t & 1;
        int nb = rb ^ 1;

        // prefetch gate pre-activations (DRAM)
        float gz[4];
        {
            const float* gp = Gp + (size_t)(eb * TT + tt) * G4 + u0 + eu;
            gz[0] = __ldg(gp);
            gz[1] = __ldg(gp + 512);
            gz[2] = __ldg(gp + 1024);
            gz[3] = __ldg(gp + 1536);
        }

        // ---- stage this warp's packed h slice ----
        {
            const uint4* srcH = (const uint4*)(d_hpk[dir][rb][0] + kp0 * 32);
            const uint4* srcL = (const uint4*)(d_hpk[dir][rb][1] + kp0 * 32);
            int r = lane >> 3;            // 0..3
            int cw = lane & 7;            // 0..7 (uint4 within 32-word row)
            #pragma unroll
            for (int i = 0; i < 8; i++) {
                int kpl = i * 4 + r;
                uint4 vh = __ldcg(srcH + kpl * 8 + cw);
                uint4 vl = __ldcg(srcL + kpl * 8 + cw);
                *(uint4*)&myHsH[kpl * 40 + cw * 4] = vh;
                *(uint4*)&myHsL[kpl * 40 + cw * 4] = vl;
            }
        }
        __syncwarp();

        // ---- 3-split bf16 MMA: z[32 batch][32 cols] over this warp's 64-k slice ----
        float acc[2][4][4];
        #pragma unroll
        for (int i = 0; i < 2; i++)
            #pragma unroll
            for (int j = 0; j < 4; j++)
                #pragma unroll
                for (int q = 0; q < 4; q++) acc[i][j][q] = 0.f;

        #pragma unroll
        for (int kt = 0; kt < 4; kt++) {
            int kb = kt * 8;
            unsigned ah[2][4], al[2][4];
            #pragma unroll
            for (int mi = 0; mi < 2; mi++) {
                int m = mi * 16 + gid;
                int o0 = (kb + tig) * 40 + m;
                int o1 = (kb + tig + 4) * 40 + m;
                ah[mi][0] = myHsH[o0];
                ah[mi][1] = myHsH[o0 + 8];
                ah[mi][2] = myHsH[o1];
                ah[mi][3] = myHsH[o1 + 8];
                al[mi][0] = myHsL[o0];
                al[mi][1] = myHsL[o0 + 8];
                al[mi][2] = myHsL[o1];
                al[mi][3] = myHsL[o1 + 8];
            }
            #pragma unroll
            for (int ni = 0; ni < 4; ni++) {
                int n = ni * 8 + gid;
                int p0 = (kp0 + kb + tig) * 40 + n;
                int p1 = p0 + 4 * 40;
                unsigned bh[2], bl[2];
                bh[0] = usH[p0];
                bh[1] = usH[p1];
                bl[0] = usL[p0];
                bl[1] = usL[p1];
                #pragma unroll
                for (int mi = 0; mi < 2; mi++) {
                    mma_bf16(acc[mi][ni], ah[mi], bh);
                    mma_bf16(acc[mi][ni], ah[mi], bl);
                    mma_bf16(acc[mi][ni], al[mi], bh);
                }
            }
        }

        // ---- write partials into own hs slice (reduction overlay) ----
        __syncwarp();
        {
            float* red = (float*)myHsH;   // [col][40] floats, 32x40 region
            #pragma unroll
            for (int mi = 0; mi < 2; mi++) {
                int row = mi * 16 + gid;
                #pragma unroll
                for (int ni = 0; ni < 4; ni++) {
                    int col = ni * 8 + tig * 2;
                    red[col * 40 + row]           = acc[mi][ni][0];
                    red[(col + 1) * 40 + row]     = acc[mi][ni][1];
                    red[col * 40 + row + 8]       = acc[mi][ni][2];
                    red[(col + 1) * 40 + row + 8] = acc[mi][ni][3];
                }
            }
        }
        __syncthreads();

        // ---- epilogue: reduce 8 warps, gates, state update ----
        {
            float z[4];
            #pragma unroll
            for (int g = 0; g < 4; g++) {
                int off = (g * 8 + eu) * 40 + eb;
                float s = gz[g];
                #pragma unroll
                for (int w8 = 0; w8 < 8; w8++)
                    s += ((float*)(hsH + w8 * 1280))[off];
                z[g] = s;
            }
            float ig = 1.f / (1.f + __expf(-z[0]));
            float fg = 1.f / (1.f + __expf(-z[1]));
            float gv = tanhf(z[2]);
            float og = 1.f / (1.f + __expf(-z[3]));
            c = fg * c + ig * gv;
            float hval = og * tanhf(c);

            unsigned short hh, hl;
            split_bf16(hval, hh, hl);
            int gu = u0 + eu;
            int kp = gu >> 1;
            int half = gu & 1;
            ((unsigned short*)d_hpk[dir][nb][0])[(kp * 32 + eb) * 2 + half] = hh;
            ((unsigned short*)d_hpk[dir][nb][1])[(kp * 32 + eb) * 2 + half] = hl;
            if (t == TT - 1) d_hout[dir][eb * HHD + gu] = hval;
        }

        // ---- per-direction grid barrier ----
        __syncthreads();
        if (tid == 0) {
            sense_local ^= 1u;
            __threadfence();
            if (atomicAdd(&g_count[dir], 1u) == DBLK - 1) {
                g_count[dir] = 0u;
                __threadfence();
                g_sense[dir] = sense_local;
            } else {
                while (g_sense[dir] != sense_local) { }
            }
            __threadfence();
        }
        __syncthreads();
    }
}

// ---------------- final concat ----------------
__global__ void final_kernel(float* __restrict__ out) {
    int i = blockIdx.x * blockDim.x + threadIdx.x;
    if (i < BB * 2 * HHD) {
        int b = i >> 10;
        int j = i & 1023;
        out[i] = (j < HHD) ? d_hout[0][b * HHD + j]
                           : d_hout[1][b * HHD + j - HHD];
    }
}

// ---------------- launch ----------------
extern "C" void kernel_launch(void* const* d_in, const int* in_sizes, int n_in,
                              void* d_out, int out_size) {
    const float* x     = (const float*)d_in[0];
    const float* gamma = (const float*)d_in[1];
    const float* beta  = (const float*)d_in[2];
    const float* mean  = (const float*)d_in[3];
    const float* var   = (const float*)d_in[4];
    const float* Wf    = (const float*)d_in[5];
    const float* Uf    = (const float*)d_in[6];
    const float* bf    = (const float*)d_in[7];
    const float* Wb    = (const float*)d_in[8];
    const float* Ub    = (const float*)d_in[9];
    const float* bb    = (const float*)d_in[10];
    float* out = (float*)d_out;

    cudaFuncSetAttribute(lstm_persist, cudaFuncAttributeMaxDynamicSharedMemorySize,
                         LSTM_SMEM);

    bn_prep_kernel<<<1, 512>>>(gamma, beta, mean, var);

    dim3 ggrid(G4 / 128, MR / 128, 2);
    gemm_tc_kernel<<<ggrid, 256>>>(x, Wf, bf, Wb, bb);

    init_kernel<<<64, 256>>>();

    lstm_persist<<<NBLK, 256, LSTM_SMEM>>>(Uf, Ub);

    final_kernel<<<128, 256>>>(out);
}

// round 7
// speedup vs baseline: 3.0837x; 1.0158x over previous
#include <cuda_runtime.h>
#include <cuda_bf16.h>
#include <math.h>

#define BB 32
#define TT 512
#define CCH 512
#define HHD 512
#define G4 2048
#define MR (BB*TT)   // 16384

#define UPB 8          // hidden units per persistent block
#define NBLK 128       // persistent grid (64 per direction)
#define DBLK 64        // blocks per direction

// ---- persistent-kernel smem layout (uint/float words) ----
#define US_H_OFF 0          // [256 kp][40] packed U hi
#define US_L_OFF 10240      // [256 kp][40] packed U lo
#define HS_H_OFF 20480      // 8 warp slices x [32 kp][40] packed h hi (red overlay)
#define HS_L_OFF 30720      // 8 warp slices x [32 kp][40] packed h lo
#define LSTM_WORDS 40960
#define LSTM_SMEM (LSTM_WORDS * 4)   // 163840 B

// ---------------- device scratch ----------------
__device__ float d_scale[CCH];
__device__ float d_shift[CCH];
__device__ float d_G[2][(size_t)MR * G4];     // 2 x 134 MB
__device__ unsigned d_xpH[(size_t)MR * 256];  // packed BN(x) hi  (16.8 MB)
__device__ unsigned d_xpL[(size_t)MR * 256];  // packed BN(x) lo
__device__ unsigned d_wpH[2][256 * G4];       // packed W hi per dir
__device__ unsigned d_wpL[2][256 * G4];       // packed W lo per dir
__device__ unsigned d_hpk[2][2][2][256 * 32]; // [dir][pingpong][hi/lo][kp*32+b]
__device__ float d_hout[2][BB * HHD];
__device__ volatile unsigned g_sense[2];
__device__ unsigned g_count[2];

// ---------------- bf16 split helpers ----------------
__device__ __forceinline__ void split_bf16(float f, unsigned short &hi, unsigned short &lo) {
    __nv_bfloat16 h = __float2bfloat16(f);
    float hf = __bfloat162float(h);
    __nv_bfloat16 l = __float2bfloat16(f - hf);
    hi = __bfloat16_as_ushort(h);
    lo = __bfloat16_as_ushort(l);
}
__device__ __forceinline__ unsigned pk16(unsigned short a, unsigned short b) {
    return (unsigned)a | ((unsigned)b << 16);
}
__device__ __forceinline__ void mma_bf16(float* d, const unsigned* a, const unsigned* b) {
    asm("mma.sync.aligned.m16n8k16.row.col.f32.bf16.bf16.f32 "
        "{%0,%1,%2,%3}, {%4,%5,%6,%7}, {%8,%9}, {%0,%1,%2,%3};"
        : "+f"(d[0]), "+f"(d[1]), "+f"(d[2]), "+f"(d[3])
        : "r"(a[0]), "r"(a[1]), "r"(a[2]), "r"(a[3]), "r"(b[0]), "r"(b[1]));
}

// ---------------- BN prep ----------------
__global__ void bn_prep_kernel(const float* __restrict__ gamma,
                               const float* __restrict__ beta,
                               const float* __restrict__ mean,
                               const float* __restrict__ var) {
    int c = threadIdx.x;
    float s = gamma[c] * rsqrtf(var[c] + 1e-3f);
    d_scale[c] = s;
    d_shift[c] = beta[c] - mean[c] * s;
}

// ---------------- pre-split BN(x) into packed bf16 hi/lo planes ----------------
__global__ void split_x_kernel(const float* __restrict__ x) {
    int i = blockIdx.x * blockDim.x + threadIdx.x;   // row*256 + kp
    int row = i >> 8, kp = i & 255;
    float2 v = *(const float2*)(x + (size_t)row * CCH + 2 * kp);
    float2 sc = *(const float2*)(d_scale + 2 * kp);
    float2 sh = *(const float2*)(d_shift + 2 * kp);
    float a = fmaf(v.x, sc.x, sh.x);
    float b = fmaf(v.y, sc.y, sh.y);
    unsigned short he, le, ho, lo;
    split_bf16(a, he, le);
    split_bf16(b, ho, lo);
    d_xpH[i] = pk16(he, ho);
    d_xpL[i] = pk16(le, lo);
}

// ---------------- pre-split W into packed bf16 hi/lo planes ----------------
__global__ void split_w_kernel(const float* __restrict__ Wf,
                               const float* __restrict__ Wb) {
    int i = blockIdx.x * blockDim.x + threadIdx.x;   // dir*(256*2048) + kp*2048 + n
    int dir = i >> 19;
    int r = i & ((1 << 19) - 1);
    int kp = r >> 11, n = r & 2047;
    const float* W = dir ? Wb : Wf;
    float e = W[(size_t)(2 * kp) * G4 + n];
    float o = W[(size_t)(2 * kp + 1) * G4 + n];
    unsigned short he, le, ho, lo;
    split_bf16(e, he, le);
    split_bf16(o, ho, lo);
    d_wpH[dir][r] = pk16(he, ho);
    d_wpL[dir][r] = pk16(le, lo);
}

// ---------------- big GEMM: G = BN(x)@W + b via 3-split bf16 mma ----------------
// Pure-copy staging from pre-split planes + register prefetch double buffering.
#define SSTR2 136

__global__ __launch_bounds__(256, 2) void gemm_tc_kernel(const float* __restrict__ bf,
                                                         const float* __restrict__ bb) {
    __shared__ unsigned AsH[8 * SSTR2], AsL[8 * SSTR2];
    __shared__ unsigned BsH[8 * SSTR2], BsL[8 * SSTR2];

    int dir = blockIdx.z;
    const float* bias = dir ? bb : bf;
    float* Out = d_G[dir];
    const unsigned* wH = d_wpH[dir];
    const unsigned* wL = d_wpL[dir];

    int tid = threadIdx.x;
    int warp = tid >> 5, lane = tid & 31;
    int gid = lane >> 2, tig = lane & 3;
    int wm = warp >> 2, wn = warp & 3;
    int rowBase = blockIdx.y * 128;
    int colBase = blockIdx.x * 128;

    // staging roles
    int aRow = tid >> 1;                 // 0..127
    int aHalf = tid & 1;                 // kp quad 0..3 or 4..7
    int bKp = tid >> 5;                  // 0..7
    int bN = (tid & 31) * 4;             // 0..124

    const unsigned* xHrow = d_xpH + (size_t)(rowBase + aRow) * 256 + aHalf * 4;
    const unsigned* xLrow = d_xpL + (size_t)(rowBase + aRow) * 256 + aHalf * 4;

    float acc[4][4][4];
    #pragma unroll
    for (int i = 0; i < 4; i++)
        #pragma unroll
        for (int j = 0; j < 4; j++)
            #pragma unroll
            for (int q = 0; q < 4; q++) acc[i][j][q] = 0.f;

    // prefetch tile 0
    uint4 raH = *(const uint4*)(xHrow);
    uint4 raL = *(const uint4*)(xLrow);
    uint4 rbH = *(const uint4*)(wH + (size_t)bKp * G4 + colBase + bN);
    uint4 rbL = *(const uint4*)(wL + (size_t)bKp * G4 + colBase + bN);

    for (int kt = 0; kt < 32; kt++) {
        // store current tile to smem
        {
            int kq = aHalf * 4;
            AsH[(kq + 0) * SSTR2 + aRow] = raH.x;
            AsH[(kq + 1) * SSTR2 + aRow] = raH.y;
            AsH[(kq + 2) * SSTR2 + aRow] = raH.z;
            AsH[(kq + 3) * SSTR2 + aRow] = raH.w;
            AsL[(kq + 0) * SSTR2 + aRow] = raL.x;
            AsL[(kq + 1) * SSTR2 + aRow] = raL.y;
            AsL[(kq + 2) * SSTR2 + aRow] = raL.z;
            AsL[(kq + 3) * SSTR2 + aRow] = raL.w;
            *(uint4*)&BsH[bKp * SSTR2 + bN] = rbH;
            *(uint4*)&BsL[bKp * SSTR2 + bN] = rbL;
        }
        __syncthreads();

        // prefetch next tile (overlaps with compute below)
        if (kt + 1 < 32) {
            int kp0 = (kt + 1) * 8;
            raH = *(const uint4*)(xHrow + kp0);
            raL = *(const uint4*)(xLrow + kp0);
            rbH = *(const uint4*)(wH + (size_t)(kp0 + bKp) * G4 + colBase + bN);
            rbL = *(const uint4*)(wL + (size_t)(kp0 + bKp) * G4 + colBase + bN);
        }

        // compute current tile
        {
            unsigned ah[4][4], al[4][4];
            #pragma unroll
            for (int mi = 0; mi < 4; mi++) {
                int m = wm * 64 + mi * 16 + gid;
                int o0 = tig * SSTR2 + m;
                int o1 = (tig + 4) * SSTR2 + m;
                ah[mi][0] = AsH[o0];
                ah[mi][1] = AsH[o0 + 8];
                ah[mi][2] = AsH[o1];
                ah[mi][3] = AsH[o1 + 8];
                al[mi][0] = AsL[o0];
                al[mi][1] = AsL[o0 + 8];
                al[mi][2] = AsL[o1];
                al[mi][3] = AsL[o1 + 8];
            }
            #pragma unroll
            for (int ni = 0; ni < 4; ni++) {
                int n = wn * 32 + ni * 8 + gid;
                unsigned bh[2], bl[2];
                bh[0] = BsH[tig * SSTR2 + n];
                bh[1] = BsH[(tig + 4) * SSTR2 + n];
                bl[0] = BsL[tig * SSTR2 + n];
                bl[1] = BsL[(tig + 4) * SSTR2 + n];
                #pragma unroll
                for (int mi = 0; mi < 4; mi++) {
                    mma_bf16(acc[mi][ni], ah[mi], bh);
                    mma_bf16(acc[mi][ni], ah[mi], bl);
                    mma_bf16(acc[mi][ni], al[mi], bh);
                }
            }
        }
        __syncthreads();
    }

    #pragma unroll
    for (int mi = 0; mi < 4; mi++) {
        int row0 = rowBase + wm * 64 + mi * 16 + gid;
        #pragma unroll
        for (int ni = 0; ni < 4; ni++) {
            int col = colBase + wn * 32 + ni * 8 + tig * 2;
            float b0 = bias[col], b1 = bias[col + 1];
            float2 v0 = make_float2(acc[mi][ni][0] + b0, acc[mi][ni][1] + b1);
            float2 v1 = make_float2(acc[mi][ni][2] + b0, acc[mi][ni][3] + b1);
            *(float2*)(Out + (size_t)row0 * G4 + col) = v0;
            *(float2*)(Out + (size_t)(row0 + 8) * G4 + col) = v1;
        }
    }
}

// ---------------- state init (zero packed h, every launch) ----------------
__global__ void init_kernel() {
    int i = blockIdx.x * blockDim.x + threadIdx.x;
    unsigned* p = &d_hpk[0][0][0][0];
    int total = 2 * 2 * 2 * 256 * 32;
    for (int j = i; j < total; j += gridDim.x * blockDim.x) p[j] = 0u;
}

// ---------------- persistent bidirectional LSTM recurrence (tensor-core) ----------------
__global__ __launch_bounds__(256, 1) void lstm_persist(const float* __restrict__ Uf,
                                                       const float* __restrict__ Ub) {
    extern __shared__ unsigned smem[];
    unsigned* usH = smem + US_H_OFF;
    unsigned* usL = smem + US_L_OFF;
    unsigned* hsH = smem + HS_H_OFF;
    unsigned* hsL = smem + HS_L_OFF;

    int tid = threadIdx.x;
    int dir = blockIdx.x >> 6;
    int blk = blockIdx.x & 63;
    int u0 = blk * UPB;
    const float* U = dir ? Ub : Uf;
    const float* Gp = d_G[dir];

    for (int i = tid; i < 256 * 32; i += 256) {
        int kp = i >> 5, j = i & 31;
        const float* up = U + (size_t)(2 * kp) * G4 + (j >> 3) * HHD + u0 + (j & 7);
        float e = up[0];
        float o = up[G4];
        unsigned short he, le, ho, lo;
        split_bf16(e, he, le);
        split_bf16(o, ho, lo);
        usH[kp * 40 + j] = pk16(he, ho);
        usL[kp * 40 + j] = pk16(le, lo);
    }

    int w = tid >> 5, lane = tid & 31;
    int gid = lane >> 2, tig = lane & 3;
    int eb = tid >> 3, eu = tid & 7;
    int kp0 = w * 32;

    unsigned* myHsH = hsH + w * 1280;
    unsigned* myHsL = hsL + w * 1280;

    float c = 0.f;
    unsigned sense_local = 0;
    __syncthreads();

    for (int t = 0; t < TT; t++) {
        int tt = dir ? (TT - 1 - t) : t;
        int rb = t & 1;
        int nb = rb ^ 1;

        float gz[4];
        {
            const float* gp = Gp + (size_t)(eb * TT + tt) * G4 + u0 + eu;
            gz[0] = __ldg(gp);
            gz[1] = __ldg(gp + 512);
            gz[2] = __ldg(gp + 1024);
            gz[3] = __ldg(gp + 1536);
        }

        {
            const uint4* srcH = (const uint4*)(d_hpk[dir][rb][0] + kp0 * 32);
            const uint4* srcL = (const uint4*)(d_hpk[dir][rb][1] + kp0 * 32);
            int r = lane >> 3;
            int cw = lane & 7;
            #pragma unroll
            for (int i = 0; i < 8; i++) {
                int kpl = i * 4 + r;
                uint4 vh = __ldcg(srcH + kpl * 8 + cw);
                uint4 vl = __ldcg(srcL + kpl * 8 + cw);
                *(uint4*)&myHsH[kpl * 40 + cw * 4] = vh;
                *(uint4*)&myHsL[kpl * 40 + cw * 4] = vl;
            }
        }
        __syncwarp();

        float acc[2][4][4];
        #pragma unroll
        for (int i = 0; i < 2; i++)
            #pragma unroll
            for (int j = 0; j < 4; j++)
                #pragma unroll
                for (int q = 0; q < 4; q++) acc[i][j][q] = 0.f;

        #pragma unroll
        for (int kt = 0; kt < 4; kt++) {
            int kb = kt * 8;
            unsigned ah[2][4], al[2][4];
            #pragma unroll
            for (int mi = 0; mi < 2; mi++) {
                int m = mi * 16 + gid;
                int o0 = (kb + tig) * 40 + m;
                int o1 = (kb + tig + 4) * 40 + m;
                ah[mi][0] = myHsH[o0];
                ah[mi][1] = myHsH[o0 + 8];
                ah[mi][2] = myHsH[o1];
                ah[mi][3] = myHsH[o1 + 8];
                al[mi][0] = myHsL[o0];
                al[mi][1] = myHsL[o0 + 8];
                al[mi][2] = myHsL[o1];
                al[mi][3] = myHsL[o1 + 8];
            }
            #pragma unroll
            for (int ni = 0; ni < 4; ni++) {
                int n = ni * 8 + gid;
                int p0 = (kp0 + kb + tig) * 40 + n;
                int p1 = p0 + 4 * 40;
                unsigned bh[2], bl[2];
                bh[0] = usH[p0];
                bh[1] = usH[p1];
                bl[0] = usL[p0];
                bl[1] = usL[p1];
                #pragma unroll
                for (int mi = 0; mi < 2; mi++) {
                    mma_bf16(acc[mi][ni], ah[mi], bh);
                    mma_bf16(acc[mi][ni], ah[mi], bl);
                    mma_bf16(acc[mi][ni], al[mi], bh);
                }
            }
        }

        __syncwarp();
        {
            float* red = (float*)myHsH;
            #pragma unroll
            for (int mi = 0; mi < 2; mi++) {
                int row = mi * 16 + gid;
                #pragma unroll
                for (int ni = 0; ni < 4; ni++) {
                    int col = ni * 8 + tig * 2;
                    red[col * 40 + row]           = acc[mi][ni][0];
                    red[(col + 1) * 40 + row]     = acc[mi][ni][1];
                    red[col * 40 + row + 8]       = acc[mi][ni][2];
                    red[(col + 1) * 40 + row + 8] = acc[mi][ni][3];
                }
            }
        }
        __syncthreads();

        {
            float z[4];
            #pragma unroll
            for (int g = 0; g < 4; g++) {
                int off = (g * 8 + eu) * 40 + eb;
                float s = gz[g];
                #pragma unroll
                for (int w8 = 0; w8 < 8; w8++)
                    s += ((float*)(hsH + w8 * 1280))[off];
                z[g] = s;
            }
            float ig = 1.f / (1.f + __expf(-z[0]));
            float fg = 1.f / (1.f + __expf(-z[1]));
            float gv = tanhf(z[2]);
            float og = 1.f / (1.f + __expf(-z[3]));
            c = fg * c + ig * gv;
            float hval = og * tanhf(c);

            unsigned short hh, hl;
            split_bf16(hval, hh, hl);
            int gu = u0 + eu;
            int kp = gu >> 1;
            int half = gu & 1;
            ((unsigned short*)d_hpk[dir][nb][0])[(kp * 32 + eb) * 2 + half] = hh;
            ((unsigned short*)d_hpk[dir][nb][1])[(kp * 32 + eb) * 2 + half] = hl;
            if (t == TT - 1) d_hout[dir][eb * HHD + gu] = hval;
        }

        __syncthreads();
        if (tid == 0) {
            sense_local ^= 1u;
            __threadfence();
            if (atomicAdd(&g_count[dir], 1u) == DBLK - 1) {
                g_count[dir] = 0u;
                __threadfence();
                g_sense[dir] = sense_local;
            } else {
                while (g_sense[dir] != sense_local) { }
            }
            __threadfence();
        }
        __syncthreads();
    }
}

// ---------------- final concat ----------------
__global__ void final_kernel(float* __restrict__ out) {
    int i = blockIdx.x * blockDim.x + threadIdx.x;
    if (i < BB * 2 * HHD) {
        int b = i >> 10;
        int j = i & 1023;
        out[i] = (j < HHD) ? d_hout[0][b * HHD + j]
                           : d_hout[1][b * HHD + j - HHD];
    }
}

// ---------------- launch ----------------
extern "C" void kernel_launch(void* const* d_in, const int* in_sizes, int n_in,
                              void* d_out, int out_size) {
    const float* x     = (const float*)d_in[0];
    const float* gamma = (const float*)d_in[1];
    const float* beta  = (const float*)d_in[2];
    const float* mean  = (const float*)d_in[3];
    const float* var   = (const float*)d_in[4];
    const float* Wf    = (const float*)d_in[5];
    const float* Uf    = (const float*)d_in[6];
    const float* bf    = (const float*)d_in[7];
    const float* Wb    = (const float*)d_in[8];
    const float* Ub    = (const float*)d_in[9];
    const float* bb    = (const float*)d_in[10];
    float* out = (float*)d_out;

    cudaFuncSetAttribute(lstm_persist, cudaFuncAttributeMaxDynamicSharedMemorySize,
                         LSTM_SMEM);

    bn_prep_kernel<<<1, 512>>>(gamma, beta, mean, var);

    split_x_kernel<<<MR * 256 / 256, 256>>>(x);
    split_w_kernel<<<2 * 256 * G4 / 256, 256>>>(Wf, Wb);

    dim3 ggrid(G4 / 128, MR / 128, 2);
    gemm_tc_kernel<<<ggrid, 256>>>(bf, bb);

    init_kernel<<<64, 256>>>();

    lstm_persist<<<NBLK, 256, LSTM_SMEM>>>(Uf, Ub);

    final_kernel<<<128, 256>>>(out);
}

// round 8
// speedup vs baseline: 3.2087x; 1.0405x over previous
#include <cuda_runtime.h>
#include <cuda_bf16.h>
#include <math.h>

#define BB 32
#define TT 512
#define CCH 512
#define HHD 512
#define G4 2048
#define MR (BB*TT)   // 16384

#define UPB 8          // hidden units per persistent block
#define NBLK 128       // persistent grid (64 per direction)
#define DBLK 64        // blocks per direction

// ---- persistent-kernel smem layout (uint/float words) ----
#define US_H_OFF 0          // [256 kp][40] packed U hi
#define US_L_OFF 10240      // [256 kp][40] packed U lo
#define HS_H_OFF 20480      // 8 warp slices x [32 kp][40] packed h hi (red overlay)
#define HS_L_OFF 30720      // 8 warp slices x [32 kp][40] packed h lo
#define LSTM_WORDS 40960
#define LSTM_SMEM (LSTM_WORDS * 4)   // 163840 B

// ---------------- device scratch ----------------
__device__ float d_scale[CCH];
__device__ float d_shift[CCH];
__device__ float d_G[2][(size_t)MR * G4];     // 2 x 134 MB
__device__ unsigned d_xpH[(size_t)MR * 256];  // packed BN(x) hi
__device__ unsigned d_xpL[(size_t)MR * 256];  // packed BN(x) lo
__device__ unsigned d_wpH[2][256 * G4];       // packed W hi per dir
__device__ unsigned d_wpL[2][256 * G4];       // packed W lo per dir
__device__ unsigned d_hpk[2][2][2][256 * 32]; // [dir][pingpong][hi/lo][kp*32+b]
__device__ float d_hout[2][BB * HHD];
__device__ volatile unsigned g_arr[2][DBLK];  // per-block step flags
__device__ volatile unsigned g_done[2];       // leader-published step

// ---------------- bf16 split helpers ----------------
__device__ __forceinline__ void split_bf16(float f, unsigned short &hi, unsigned short &lo) {
    __nv_bfloat16 h = __float2bfloat16(f);
    float hf = __bfloat162float(h);
    __nv_bfloat16 l = __float2bfloat16(f - hf);
    hi = __bfloat16_as_ushort(h);
    lo = __bfloat16_as_ushort(l);
}
__device__ __forceinline__ unsigned pk16(unsigned short a, unsigned short b) {
    return (unsigned)a | ((unsigned)b << 16);
}
__device__ __forceinline__ void mma_bf16(float* d, const unsigned* a, const unsigned* b) {
    asm("mma.sync.aligned.m16n8k16.row.col.f32.bf16.bf16.f32 "
        "{%0,%1,%2,%3}, {%4,%5,%6,%7}, {%8,%9}, {%0,%1,%2,%3};"
        : "+f"(d[0]), "+f"(d[1]), "+f"(d[2]), "+f"(d[3])
        : "r"(a[0]), "r"(a[1]), "r"(a[2]), "r"(a[3]), "r"(b[0]), "r"(b[1]));
}

// ---------------- fast activations (error ~1e-6, clamped) ----------------
__device__ __forceinline__ float fsigmoid(float z) {
    return __fdividef(1.f, 1.f + __expf(-z));
}
__device__ __forceinline__ float ftanh(float z) {
    z = fminf(fmaxf(z, -15.f), 15.f);
    float e = __expf(2.f * z);
    return __fdividef(e - 1.f, e + 1.f);
}

// ---------------- BN prep ----------------
__global__ void bn_prep_kernel(const float* __restrict__ gamma,
                               const float* __restrict__ beta,
                               const float* __restrict__ mean,
                               const float* __restrict__ var) {
    int c = threadIdx.x;
    float s = gamma[c] * rsqrtf(var[c] + 1e-3f);
    d_scale[c] = s;
    d_shift[c] = beta[c] - mean[c] * s;
}

// ---------------- pre-split BN(x) into packed bf16 hi/lo planes ----------------
__global__ void split_x_kernel(const float* __restrict__ x) {
    int i = blockIdx.x * blockDim.x + threadIdx.x;
    int row = i >> 8, kp = i & 255;
    float2 v = *(const float2*)(x + (size_t)row * CCH + 2 * kp);
    float2 sc = *(const float2*)(d_scale + 2 * kp);
    float2 sh = *(const float2*)(d_shift + 2 * kp);
    float a = fmaf(v.x, sc.x, sh.x);
    float b = fmaf(v.y, sc.y, sh.y);
    unsigned short he, le, ho, lo;
    split_bf16(a, he, le);
    split_bf16(b, ho, lo);
    d_xpH[i] = pk16(he, ho);
    d_xpL[i] = pk16(le, lo);
}

// ---------------- pre-split W into packed bf16 hi/lo planes ----------------
__global__ void split_w_kernel(const float* __restrict__ Wf,
                               const float* __restrict__ Wb) {
    int i = blockIdx.x * blockDim.x + threadIdx.x;
    int dir = i >> 19;
    int r = i & ((1 << 19) - 1);
    int kp = r >> 11, n = r & 2047;
    const float* W = dir ? Wb : Wf;
    float e = W[(size_t)(2 * kp) * G4 + n];
    float o = W[(size_t)(2 * kp + 1) * G4 + n];
    unsigned short he, le, ho, lo;
    split_bf16(e, he, le);
    split_bf16(o, ho, lo);
    d_wpH[dir][r] = pk16(he, ho);
    d_wpL[dir][r] = pk16(le, lo);
}

// ---------------- big GEMM: G = BN(x)@W + b via 3-split bf16 mma ----------------
#define SSTR2 136

__global__ __launch_bounds__(256, 2) void gemm_tc_kernel(const float* __restrict__ bf,
                                                         const float* __restrict__ bb) {
    __shared__ unsigned AsH[8 * SSTR2], AsL[8 * SSTR2];
    __shared__ unsigned BsH[8 * SSTR2], BsL[8 * SSTR2];

    int dir = blockIdx.z;
    const float* bias = dir ? bb : bf;
    float* Out = d_G[dir];
    const unsigned* wH = d_wpH[dir];
    const unsigned* wL = d_wpL[dir];

    int tid = threadIdx.x;
    int warp = tid >> 5, lane = tid & 31;
    int gid = lane >> 2, tig = lane & 3;
    int wm = warp >> 2, wn = warp & 3;
    int rowBase = blockIdx.y * 128;
    int colBase = blockIdx.x * 128;

    int aRow = tid >> 1;
    int aHalf = tid & 1;
    int bKp = tid >> 5;
    int bN = (tid & 31) * 4;

    const unsigned* xHrow = d_xpH + (size_t)(rowBase + aRow) * 256 + aHalf * 4;
    const unsigned* xLrow = d_xpL + (size_t)(rowBase + aRow) * 256 + aHalf * 4;

    float acc[4][4][4];
    #pragma unroll
    for (int i = 0; i < 4; i++)
        #pragma unroll
        for (int j = 0; j < 4; j++)
            #pragma unroll
            for (int q = 0; q < 4; q++) acc[i][j][q] = 0.f;

    uint4 raH = *(const uint4*)(xHrow);
    uint4 raL = *(const uint4*)(xLrow);
    uint4 rbH = *(const uint4*)(wH + (size_t)bKp * G4 + colBase + bN);
    uint4 rbL = *(const uint4*)(wL + (size_t)bKp * G4 + colBase + bN);

    for (int kt = 0; kt < 32; kt++) {
        {
            int kq = aHalf * 4;
            AsH[(kq + 0) * SSTR2 + aRow] = raH.x;
            AsH[(kq + 1) * SSTR2 + aRow] = raH.y;
            AsH[(kq + 2) * SSTR2 + aRow] = raH.z;
            AsH[(kq + 3) * SSTR2 + aRow] = raH.w;
            AsL[(kq + 0) * SSTR2 + aRow] = raL.x;
            AsL[(kq + 1) * SSTR2 + aRow] = raL.y;
            AsL[(kq + 2) * SSTR2 + aRow] = raL.z;
            AsL[(kq + 3) * SSTR2 + aRow] = raL.w;
            *(uint4*)&BsH[bKp * SSTR2 + bN] = rbH;
            *(uint4*)&BsL[bKp * SSTR2 + bN] = rbL;
        }
        __syncthreads();

        if (kt + 1 < 32) {
            int kp0 = (kt + 1) * 8;
            raH = *(const uint4*)(xHrow + kp0);
            raL = *(const uint4*)(xLrow + kp0);
            rbH = *(const uint4*)(wH + (size_t)(kp0 + bKp) * G4 + colBase + bN);
            rbL = *(const uint4*)(wL + (size_t)(kp0 + bKp) * G4 + colBase + bN);
        }

        {
            unsigned ah[4][4], al[4][4];
            #pragma unroll
            for (int mi = 0; mi < 4; mi++) {
                int m = wm * 64 + mi * 16 + gid;
                int o0 = tig * SSTR2 + m;
                int o1 = (tig + 4) * SSTR2 + m;
                ah[mi][0] = AsH[o0];
                ah[mi][1] = AsH[o0 + 8];
                ah[mi][2] = AsH[o1];
                ah[mi][3] = AsH[o1 + 8];
                al[mi][0] = AsL[o0];
                al[mi][1] = AsL[o0 + 8];
                al[mi][2] = AsL[o1];
                al[mi][3] = AsL[o1 + 8];
            }
            #pragma unroll
            for (int ni = 0; ni < 4; ni++) {
                int n = wn * 32 + ni * 8 + gid;
                unsigned bh[2], bl[2];
                bh[0] = BsH[tig * SSTR2 + n];
                bh[1] = BsH[(tig + 4) * SSTR2 + n];
                bl[0] = BsL[tig * SSTR2 + n];
                bl[1] = BsL[(tig + 4) * SSTR2 + n];
                #pragma unroll
                for (int mi = 0; mi < 4; mi++) {
                    mma_bf16(acc[mi][ni], ah[mi], bh);
                    mma_bf16(acc[mi][ni], ah[mi], bl);
                    mma_bf16(acc[mi][ni], al[mi], bh);
                }
            }
        }
        __syncthreads();
    }

    #pragma unroll
    for (int mi = 0; mi < 4; mi++) {
        int row0 = rowBase + wm * 64 + mi * 16 + gid;
        #pragma unroll
        for (int ni = 0; ni < 4; ni++) {
            int col = colBase + wn * 32 + ni * 8 + tig * 2;
            float b0 = bias[col], b1 = bias[col + 1];
            float2 v0 = make_float2(acc[mi][ni][0] + b0, acc[mi][ni][1] + b1);
            float2 v1 = make_float2(acc[mi][ni][2] + b0, acc[mi][ni][3] + b1);
            *(float2*)(Out + (size_t)row0 * G4 + col) = v0;
            *(float2*)(Out + (size_t)(row0 + 8) * G4 + col) = v1;
        }
    }
}

// ---------------- state init (zero packed h + barrier flags, every launch) ----------------
__global__ void init_kernel() {
    int i = blockIdx.x * blockDim.x + threadIdx.x;
    unsigned* p = &d_hpk[0][0][0][0];
    int total = 2 * 2 * 2 * 256 * 32;
    for (int j = i; j < total; j += gridDim.x * blockDim.x) p[j] = 0u;
    if (i < 2 * DBLK) ((volatile unsigned*)&g_arr[0][0])[i] = 0u;
    if (i < 2) g_done[i] = 0u;
}

// ---------------- persistent bidirectional LSTM recurrence (tensor-core) ----------------
__global__ __launch_bounds__(256, 1) void lstm_persist(const float* __restrict__ Uf,
                                                       const float* __restrict__ Ub) {
    extern __shared__ unsigned smem[];
    unsigned* usH = smem + US_H_OFF;
    unsigned* usL = smem + US_L_OFF;
    unsigned* hsH = smem + HS_H_OFF;
    unsigned* hsL = smem + HS_L_OFF;

    int tid = threadIdx.x;
    int dir = blockIdx.x >> 6;
    int blk = blockIdx.x & 63;
    int u0 = blk * UPB;
    const float* U = dir ? Ub : Uf;
    const float* Gp = d_G[dir];

    for (int i = tid; i < 256 * 32; i += 256) {
        int kp = i >> 5, j = i & 31;
        const float* up = U + (size_t)(2 * kp) * G4 + (j >> 3) * HHD + u0 + (j & 7);
        float e = up[0];
        float o = up[G4];
        unsigned short he, le, ho, lo;
        split_bf16(e, he, le);
        split_bf16(o, ho, lo);
        usH[kp * 40 + j] = pk16(he, ho);
        usL[kp * 40 + j] = pk16(le, lo);
    }

    int w = tid >> 5, lane = tid & 31;
    int gid = lane >> 2, tig = lane & 3;
    int eb = tid >> 3, eu = tid & 7;
    int kp0 = w * 32;

    unsigned* myHsH = hsH + w * 1280;
    unsigned* myHsL = hsL + w * 1280;

    float c = 0.f;
    __syncthreads();

    // prefetch gate pre-activations for t=0
    float gzc[4];
    {
        int tt0 = dir ? (TT - 1) : 0;
        const float* gp = Gp + (size_t)(eb * TT + tt0) * G4 + u0 + eu;
        gzc[0] = __ldg(gp);
        gzc[1] = __ldg(gp + 512);
        gzc[2] = __ldg(gp + 1024);
        gzc[3] = __ldg(gp + 1536);
    }

    for (int t = 0; t < TT; t++) {
        int rb = t & 1;
        int nb = rb ^ 1;

        // ---- stage this warp's packed h slice ----
        {
            const uint4* srcH = (const uint4*)(d_hpk[dir][rb][0] + kp0 * 32);
            const uint4* srcL = (const uint4*)(d_hpk[dir][rb][1] + kp0 * 32);
            int r = lane >> 3;
            int cw = lane & 7;
            #pragma unroll
            for (int i = 0; i < 8; i++) {
                int kpl = i * 4 + r;
                uint4 vh = __ldcg(srcH + kpl * 8 + cw);
                uint4 vl = __ldcg(srcL + kpl * 8 + cw);
                *(uint4*)&myHsH[kpl * 40 + cw * 4] = vh;
                *(uint4*)&myHsL[kpl * 40 + cw * 4] = vl;
            }
        }
        __syncwarp();

        // ---- 3-split bf16 MMA over this warp's 64-k slice ----
        float acc[2][4][4];
        #pragma unroll
        for (int i = 0; i < 2; i++)
            #pragma unroll
            for (int j = 0; j < 4; j++)
                #pragma unroll
                for (int q = 0; q < 4; q++) acc[i][j][q] = 0.f;

        #pragma unroll
        for (int kt = 0; kt < 4; kt++) {
            int kb = kt * 8;
            unsigned ah[2][4], al[2][4];
            #pragma unroll
            for (int mi = 0; mi < 2; mi++) {
                int m = mi * 16 + gid;
                int o0 = (kb + tig) * 40 + m;
                int o1 = (kb + tig + 4) * 40 + m;
                ah[mi][0] = myHsH[o0];
                ah[mi][1] = myHsH[o0 + 8];
                ah[mi][2] = myHsH[o1];
                ah[mi][3] = myHsH[o1 + 8];
                al[mi][0] = myHsL[o0];
                al[mi][1] = myHsL[o0 + 8];
                al[mi][2] = myHsL[o1];
                al[mi][3] = myHsL[o1 + 8];
            }
            #pragma unroll
            for (int ni = 0; ni < 4; ni++) {
                int n = ni * 8 + gid;
                int p0 = (kp0 + kb + tig) * 40 + n;
                int p1 = p0 + 4 * 40;
                unsigned bh[2], bl[2];
                bh[0] = usH[p0];
                bh[1] = usH[p1];
                bl[0] = usL[p0];
                bl[1] = usL[p1];
                #pragma unroll
                for (int mi = 0; mi < 2; mi++) {
                    mma_bf16(acc[mi][ni], ah[mi], bh);
                    mma_bf16(acc[mi][ni], ah[mi], bl);
                    mma_bf16(acc[mi][ni], al[mi], bh);
                }
            }
        }

        // ---- write partials into own hs slice (reduction overlay) ----
        __syncwarp();
        {
            float* red = (float*)myHsH;
            #pragma unroll
            for (int mi = 0; mi < 2; mi++) {
                int row = mi * 16 + gid;
                #pragma unroll
                for (int ni = 0; ni < 4; ni++) {
                    int col = ni * 8 + tig * 2;
                    red[col * 40 + row]           = acc[mi][ni][0];
                    red[(col + 1) * 40 + row]     = acc[mi][ni][1];
                    red[col * 40 + row + 8]       = acc[mi][ni][2];
                    red[(col + 1) * 40 + row + 8] = acc[mi][ni][3];
                }
            }
        }

        // prefetch next step's gate pre-activations (hidden under epilogue+barrier)
        float gzn[4] = {0.f, 0.f, 0.f, 0.f};
        if (t + 1 < TT) {
            int ttn = dir ? (TT - 2 - t) : (t + 1);
            const float* gp = Gp + (size_t)(eb * TT + ttn) * G4 + u0 + eu;
            gzn[0] = __ldg(gp);
            gzn[1] = __ldg(gp + 512);
            gzn[2] = __ldg(gp + 1024);
            gzn[3] = __ldg(gp + 1536);
        }
        __syncthreads();

        // ---- epilogue: reduce 8 warps, gates, state update ----
        {
            float z[4];
            #pragma unroll
            for (int g = 0; g < 4; g++) {
                int off = (g * 8 + eu) * 40 + eb;
                float s = gzc[g];
                #pragma unroll
                for (int w8 = 0; w8 < 8; w8++)
                    s += ((float*)(hsH + w8 * 1280))[off];
                z[g] = s;
            }
            float ig = fsigmoid(z[0]);
            float fg = fsigmoid(z[1]);
            float gv = ftanh(z[2]);
            float og = fsigmoid(z[3]);
            c = fg * c + ig * gv;
            float hval = og * ftanh(c);

            unsigned short hh, hl;
            split_bf16(hval, hh, hl);
            int gu = u0 + eu;
            int kp = gu >> 1;
            int half = gu & 1;
            ((unsigned short*)d_hpk[dir][nb][0])[(kp * 32 + eb) * 2 + half] = hh;
            ((unsigned short*)d_hpk[dir][nb][1])[(kp * 32 + eb) * 2 + half] = hl;
            if (t == TT - 1) d_hout[dir][eb * HHD + gu] = hval;
        }

        gzc[0] = gzn[0]; gzc[1] = gzn[1]; gzc[2] = gzn[2]; gzc[3] = gzn[3];

        // ---- atomic-free flag-array grid barrier (per direction) ----
        __syncthreads();
        if (tid == 0) {
            __threadfence();
            g_arr[dir][blk] = t + 1;
        }
        if (blk == 0) {
            if (tid < DBLK) {
                while (g_arr[dir][tid] < (unsigned)(t + 1)) { }
            }
            __syncthreads();
            if (tid == 0) {
                __threadfence();
                g_done[dir] = t + 1;
            }
        }
        if (tid == 0) {
            while (g_done[dir] < (unsigned)(t + 1)) { }
            __threadfence();
        }
        __syncthreads();
    }
}

// ---------------- final concat ----------------
__global__ void final_kernel(float* __restrict__ out) {
    int i = blockIdx.x * blockDim.x + threadIdx.x;
    if (i < BB * 2 * HHD) {
        int b = i >> 10;
        int j = i & 1023;
        out[i] = (j < HHD) ? d_hout[0][b * HHD + j]
                           : d_hout[1][b * HHD + j - HHD];
    }
}

// ---------------- launch ----------------
extern "C" void kernel_launch(void* const* d_in, const int* in_sizes, int n_in,
                              void* d_out, int out_size) {
    const float* x     = (const float*)d_in[0];
    const float* gamma = (const float*)d_in[1];
    const float* beta  = (const float*)d_in[2];
    const float* mean  = (const float*)d_in[3];
    const float* var   = (const float*)d_in[4];
    const float* Wf    = (const float*)d_in[5];
    const float* Uf    = (const float*)d_in[6];
    const float* bf    = (const float*)d_in[7];
    const float* Wb    = (const float*)d_in[8];
    const float* Ub    = (const float*)d_in[9];
    const float* bb    = (const float*)d_in[10];
    float* out = (float*)d_out;

    cudaFuncSetAttribute(lstm_persist, cudaFuncAttributeMaxDynamicSharedMemorySize,
                         LSTM_SMEM);

    bn_prep_kernel<<<1, 512>>>(gamma, beta, mean, var);

    split_x_kernel<<<MR * 256 / 256, 256>>>(x);
    split_w_kernel<<<2 * 256 * G4 / 256, 256>>>(Wf, Wb);

    dim3 ggrid(G4 / 128, MR / 128, 2);
    gemm_tc_kernel<<<ggrid, 256>>>(bf, bb);

    init_kernel<<<64, 256>>>();

    lstm_persist<<<NBLK, 256, LSTM_SMEM>>>(Uf, Ub);

    final_kernel<<<128, 256>>>(out);
}

// round 9
// speedup vs baseline: 3.3393x; 1.0407x over previous
#include <cuda_runtime.h>
#include <cuda_bf16.h>
#include <math.h>

#define BB 32
#define TT 512
#define CCH 512
#define HHD 512
#define G4 2048
#define MR (BB*TT)   // 16384

#define UPB 8          // hidden units per persistent block
#define NBLK 128       // persistent grid (64 per direction)
#define DBLK 64        // blocks per direction

// ---- persistent-kernel smem layout (uint/float words) ----
#define US_H_OFF 0          // [256 kp][40] packed U hi
#define US_L_OFF 10240      // [256 kp][40] packed U lo
#define HS_H_OFF 20480      // 8 warp slices x [32 kp][40] packed h hi (red overlay)
#define HS_L_OFF 30720      // 8 warp slices x [32 kp][40] packed h lo
#define LSTM_WORDS 40960
#define LSTM_SMEM (LSTM_WORDS * 4)   // 163840 B

// ---------------- device scratch ----------------
__device__ float d_scale[CCH];
__device__ float d_shift[CCH];
__device__ float d_G[2][(size_t)MR * G4];     // 2 x 134 MB
__device__ unsigned d_xpH[(size_t)MR * 256];  // packed BN(x) hi
__device__ unsigned d_xpL[(size_t)MR * 256];  // packed BN(x) lo
__device__ unsigned d_wpH[2][256 * G4];       // packed W hi per dir
__device__ unsigned d_wpL[2][256 * G4];       // packed W lo per dir
__device__ unsigned d_hpk[2][2][2][256 * 32]; // [dir][pingpong][hi/lo][kp*32+b]
__device__ float d_hout[2][BB * HHD];
__device__ volatile unsigned g_arr[2][DBLK];  // per-block step flags
__device__ volatile unsigned g_done[2];       // leader-published step

// ---------------- bf16 split helpers ----------------
__device__ __forceinline__ void split_bf16(float f, unsigned short &hi, unsigned short &lo) {
    __nv_bfloat16 h = __float2bfloat16(f);
    float hf = __bfloat162float(h);
    __nv_bfloat16 l = __float2bfloat16(f - hf);
    hi = __bfloat16_as_ushort(h);
    lo = __bfloat16_as_ushort(l);
}
__device__ __forceinline__ unsigned pk16(unsigned short a, unsigned short b) {
    return (unsigned)a | ((unsigned)b << 16);
}
__device__ __forceinline__ void mma_bf16(float* d, const unsigned* a, const unsigned* b) {
    asm("mma.sync.aligned.m16n8k16.row.col.f32.bf16.bf16.f32 "
        "{%0,%1,%2,%3}, {%4,%5,%6,%7}, {%8,%9}, {%0,%1,%2,%3};"
        : "+f"(d[0]), "+f"(d[1]), "+f"(d[2]), "+f"(d[3])
        : "r"(a[0]), "r"(a[1]), "r"(a[2]), "r"(a[3]), "r"(b[0]), "r"(b[1]));
}

// ---------------- fast activations ----------------
__device__ __forceinline__ float fsigmoid(float z) {
    return __fdividef(1.f, 1.f + __expf(-z));
}
__device__ __forceinline__ float ftanh(float z) {
    z = fminf(fmaxf(z, -15.f), 15.f);
    float e = __expf(2.f * z);
    return __fdividef(e - 1.f, e + 1.f);
}

// ---------------- BN prep ----------------
__global__ void bn_prep_kernel(const float* __restrict__ gamma,
                               const float* __restrict__ beta,
                               const float* __restrict__ mean,
                               const float* __restrict__ var) {
    int c = threadIdx.x;
    float s = gamma[c] * rsqrtf(var[c] + 1e-3f);
    d_scale[c] = s;
    d_shift[c] = beta[c] - mean[c] * s;
}

// ---------------- pre-split BN(x) into packed bf16 hi/lo planes ----------------
__global__ void split_x_kernel(const float* __restrict__ x) {
    int i = blockIdx.x * blockDim.x + threadIdx.x;
    int row = i >> 8, kp = i & 255;
    float2 v = *(const float2*)(x + (size_t)row * CCH + 2 * kp);
    float2 sc = *(const float2*)(d_scale + 2 * kp);
    float2 sh = *(const float2*)(d_shift + 2 * kp);
    float a = fmaf(v.x, sc.x, sh.x);
    float b = fmaf(v.y, sc.y, sh.y);
    unsigned short he, le, ho, lo;
    split_bf16(a, he, le);
    split_bf16(b, ho, lo);
    d_xpH[i] = pk16(he, ho);
    d_xpL[i] = pk16(le, lo);
}

// ---------------- pre-split W into packed bf16 hi/lo planes ----------------
__global__ void split_w_kernel(const float* __restrict__ Wf,
                               const float* __restrict__ Wb) {
    int i = blockIdx.x * blockDim.x + threadIdx.x;
    int dir = i >> 19;
    int r = i & ((1 << 19) - 1);
    int kp = r >> 11, n = r & 2047;
    const float* W = dir ? Wb : Wf;
    float e = W[(size_t)(2 * kp) * G4 + n];
    float o = W[(size_t)(2 * kp + 1) * G4 + n];
    unsigned short he, le, ho, lo;
    split_bf16(e, he, le);
    split_bf16(o, ho, lo);
    d_wpH[dir][r] = pk16(he, ho);
    d_wpL[dir][r] = pk16(le, lo);
}

// ---------------- big GEMM: G = BN(x)@W + b via 3-split bf16 mma ----------------
#define SSTR2 136

__global__ __launch_bounds__(256, 2) void gemm_tc_kernel(const float* __restrict__ bf,
                                                         const float* __restrict__ bb) {
    __shared__ unsigned AsH[8 * SSTR2], AsL[8 * SSTR2];
    __shared__ unsigned BsH[8 * SSTR2], BsL[8 * SSTR2];

    int dir = blockIdx.z;
    const float* bias = dir ? bb : bf;
    float* Out = d_G[dir];
    const unsigned* wH = d_wpH[dir];
    const unsigned* wL = d_wpL[dir];

    int tid = threadIdx.x;
    int warp = tid >> 5, lane = tid & 31;
    int gid = lane >> 2, tig = lane & 3;
    int wm = warp >> 2, wn = warp & 3;
    int rowBase = blockIdx.y * 128;
    int colBase = blockIdx.x * 128;

    int aRow = tid >> 1;
    int aHalf = tid & 1;
    int bKp = tid >> 5;
    int bN = (tid & 31) * 4;

    const unsigned* xHrow = d_xpH + (size_t)(rowBase + aRow) * 256 + aHalf * 4;
    const unsigned* xLrow = d_xpL + (size_t)(rowBase + aRow) * 256 + aHalf * 4;

    float acc[4][4][4];
    #pragma unroll
    for (int i = 0; i < 4; i++)
        #pragma unroll
        for (int j = 0; j < 4; j++)
            #pragma unroll
            for (int q = 0; q < 4; q++) acc[i][j][q] = 0.f;

    uint4 raH = *(const uint4*)(xHrow);
    uint4 raL = *(const uint4*)(xLrow);
    uint4 rbH = *(const uint4*)(wH + (size_t)bKp * G4 + colBase + bN);
    uint4 rbL = *(const uint4*)(wL + (size_t)bKp * G4 + colBase + bN);

    for (int kt = 0; kt < 32; kt++) {
        {
            int kq = aHalf * 4;
            AsH[(kq + 0) * SSTR2 + aRow] = raH.x;
            AsH[(kq + 1) * SSTR2 + aRow] = raH.y;
            AsH[(kq + 2) * SSTR2 + aRow] = raH.z;
            AsH[(kq + 3) * SSTR2 + aRow] = raH.w;
            AsL[(kq + 0) * SSTR2 + aRow] = raL.x;
            AsL[(kq + 1) * SSTR2 + aRow] = raL.y;
            AsL[(kq + 2) * SSTR2 + aRow] = raL.z;
            AsL[(kq + 3) * SSTR2 + aRow] = raL.w;
            *(uint4*)&BsH[bKp * SSTR2 + bN] = rbH;
            *(uint4*)&BsL[bKp * SSTR2 + bN] = rbL;
        }
        __syncthreads();

        if (kt + 1 < 32) {
            int kp0 = (kt + 1) * 8;
            raH = *(const uint4*)(xHrow + kp0);
            raL = *(const uint4*)(xLrow + kp0);
            rbH = *(const uint4*)(wH + (size_t)(kp0 + bKp) * G4 + colBase + bN);
            rbL = *(const uint4*)(wL + (size_t)(kp0 + bKp) * G4 + colBase + bN);
        }

        {
            unsigned ah[4][4], al[4][4];
            #pragma unroll
            for (int mi = 0; mi < 4; mi++) {
                int m = wm * 64 + mi * 16 + gid;
                int o0 = tig * SSTR2 + m;
                int o1 = (tig + 4) * SSTR2 + m;
                ah[mi][0] = AsH[o0];
                ah[mi][1] = AsH[o0 + 8];
                ah[mi][2] = AsH[o1];
                ah[mi][3] = AsH[o1 + 8];
                al[mi][0] = AsL[o0];
                al[mi][1] = AsL[o0 + 8];
                al[mi][2] = AsL[o1];
                al[mi][3] = AsL[o1 + 8];
            }
            #pragma unroll
            for (int ni = 0; ni < 4; ni++) {
                int n = wn * 32 + ni * 8 + gid;
                unsigned bh[2], bl[2];
                bh[0] = BsH[tig * SSTR2 + n];
                bh[1] = BsH[(tig + 4) * SSTR2 + n];
                bl[0] = BsL[tig * SSTR2 + n];
                bl[1] = BsL[(tig + 4) * SSTR2 + n];
                #pragma unroll
                for (int mi = 0; mi < 4; mi++) {
                    mma_bf16(acc[mi][ni], ah[mi], bh);
                    mma_bf16(acc[mi][ni], ah[mi], bl);
                    mma_bf16(acc[mi][ni], al[mi], bh);
                }
            }
        }
        __syncthreads();
    }

    #pragma unroll
    for (int mi = 0; mi < 4; mi++) {
        int row0 = rowBase + wm * 64 + mi * 16 + gid;
        #pragma unroll
        for (int ni = 0; ni < 4; ni++) {
            int col = colBase + wn * 32 + ni * 8 + tig * 2;
            float b0 = bias[col], b1 = bias[col + 1];
            float2 v0 = make_float2(acc[mi][ni][0] + b0, acc[mi][ni][1] + b1);
            float2 v1 = make_float2(acc[mi][ni][2] + b0, acc[mi][ni][3] + b1);
            *(float2*)(Out + (size_t)row0 * G4 + col) = v0;
            *(float2*)(Out + (size_t)(row0 + 8) * G4 + col) = v1;
        }
    }
}

// ---------------- state init ----------------
__global__ void init_kernel() {
    int i = blockIdx.x * blockDim.x + threadIdx.x;
    unsigned* p = &d_hpk[0][0][0][0];
    int total = 2 * 2 * 2 * 256 * 32;
    for (int j = i; j < total; j += gridDim.x * blockDim.x) p[j] = 0u;
    if (i < 2 * DBLK) ((volatile unsigned*)&g_arr[0][0])[i] = 0u;
    if (i < 2) g_done[i] = 0u;
}

// ---------------- persistent bidirectional LSTM recurrence (tensor-core) ----------------
__global__ __launch_bounds__(256, 1) void lstm_persist(const float* __restrict__ Uf,
                                                       const float* __restrict__ Ub) {
    extern __shared__ unsigned smem[];
    unsigned* usH = smem + US_H_OFF;
    unsigned* usL = smem + US_L_OFF;
    unsigned* hsH = smem + HS_H_OFF;
    unsigned* hsL = smem + HS_L_OFF;

    int tid = threadIdx.x;
    int dir = blockIdx.x >> 6;
    int blk = blockIdx.x & 63;
    int u0 = blk * UPB;
    const float* U = dir ? Ub : Uf;
    const float* Gp = d_G[dir];

    for (int i = tid; i < 256 * 32; i += 256) {
        int kp = i >> 5, j = i & 31;
        const float* up = U + (size_t)(2 * kp) * G4 + (j >> 3) * HHD + u0 + (j & 7);
        float e = up[0];
        float o = up[G4];
        unsigned short he, le, ho, lo;
        split_bf16(e, he, le);
        split_bf16(o, ho, lo);
        usH[kp * 40 + j] = pk16(he, ho);
        usL[kp * 40 + j] = pk16(le, lo);
    }

    int w = tid >> 5, lane = tid & 31;
    int gid = lane >> 2, tig = lane & 3;
    int eb = tid >> 3, eu = tid & 7;
    int kp0 = w * 32;

    unsigned* myHsH = hsH + w * 1280;
    unsigned* myHsL = hsL + w * 1280;

    float c = 0.f;
    __syncthreads();

    float gzc[4];
    {
        int tt0 = dir ? (TT - 1) : 0;
        const float* gp = Gp + (size_t)(eb * TT + tt0) * G4 + u0 + eu;
        gzc[0] = __ldg(gp);
        gzc[1] = __ldg(gp + 512);
        gzc[2] = __ldg(gp + 1024);
        gzc[3] = __ldg(gp + 1536);
    }

    for (int t = 0; t < TT; t++) {
        int rb = t & 1;
        int nb = rb ^ 1;

        // ---- stage this warp's packed h slice ----
        {
            const uint4* srcH = (const uint4*)(d_hpk[dir][rb][0] + kp0 * 32);
            const uint4* srcL = (const uint4*)(d_hpk[dir][rb][1] + kp0 * 32);
            int r = lane >> 3;
            int cw = lane & 7;
            #pragma unroll
            for (int i = 0; i < 8; i++) {
                int kpl = i * 4 + r;
                uint4 vh = __ldcg(srcH + kpl * 8 + cw);
                uint4 vl = __ldcg(srcL + kpl * 8 + cw);
                *(uint4*)&myHsH[kpl * 40 + cw * 4] = vh;
                *(uint4*)&myHsL[kpl * 40 + cw * 4] = vl;
            }
        }
        __syncwarp();

        // ---- 3-split bf16 MMA with 2 independent accumulator sets ----
        float aM[2][4][4], aC[2][4][4];
        #pragma unroll
        for (int i = 0; i < 2; i++)
            #pragma unroll
            for (int j = 0; j < 4; j++)
                #pragma unroll
                for (int q = 0; q < 4; q++) { aM[i][j][q] = 0.f; aC[i][j][q] = 0.f; }

        #pragma unroll
        for (int kt = 0; kt < 4; kt++) {
            int kb = kt * 8;
            unsigned ah[2][4], al[2][4];
            #pragma unroll
            for (int mi = 0; mi < 2; mi++) {
                int m = mi * 16 + gid;
                int o0 = (kb + tig) * 40 + m;
                int o1 = (kb + tig + 4) * 40 + m;
                ah[mi][0] = myHsH[o0];
                ah[mi][1] = myHsH[o0 + 8];
                ah[mi][2] = myHsH[o1];
                ah[mi][3] = myHsH[o1 + 8];
                al[mi][0] = myHsL[o0];
                al[mi][1] = myHsL[o0 + 8];
                al[mi][2] = myHsL[o1];
                al[mi][3] = myHsL[o1 + 8];
            }
            #pragma unroll
            for (int ni = 0; ni < 4; ni++) {
                int n = ni * 8 + gid;
                int p0 = (kp0 + kb + tig) * 40 + n;
                int p1 = p0 + 4 * 40;
                unsigned bh[2], bl[2];
                bh[0] = usH[p0];
                bh[1] = usH[p1];
                bl[0] = usL[p0];
                bl[1] = usL[p1];
                #pragma unroll
                for (int mi = 0; mi < 2; mi++) {
                    mma_bf16(aM[mi][ni], ah[mi], bh);   // main chain (indep)
                    mma_bf16(aC[mi][ni], ah[mi], bl);   // correction chain
                    mma_bf16(aC[mi][ni], al[mi], bh);
                }
            }
        }

        // ---- combine + write partials into own hs slice ----
        __syncwarp();
        {
            float* red = (float*)myHsH;
            #pragma unroll
            for (int mi = 0; mi < 2; mi++) {
                int row = mi * 16 + gid;
                #pragma unroll
                for (int ni = 0; ni < 4; ni++) {
                    int col = ni * 8 + tig * 2;
                    red[col * 40 + row]           = aM[mi][ni][0] + aC[mi][ni][0];
                    red[(col + 1) * 40 + row]     = aM[mi][ni][1] + aC[mi][ni][1];
                    red[col * 40 + row + 8]       = aM[mi][ni][2] + aC[mi][ni][2];
                    red[(col + 1) * 40 + row + 8] = aM[mi][ni][3] + aC[mi][ni][3];
                }
            }
        }

        // prefetch next step's gate pre-activations
        float gzn[4] = {0.f, 0.f, 0.f, 0.f};
        if (t + 1 < TT) {
            int ttn = dir ? (TT - 2 - t) : (t + 1);
            const float* gp = Gp + (size_t)(eb * TT + ttn) * G4 + u0 + eu;
            gzn[0] = __ldg(gp);
            gzn[1] = __ldg(gp + 512);
            gzn[2] = __ldg(gp + 1024);
            gzn[3] = __ldg(gp + 1536);
        }
        __syncthreads();

        // ---- epilogue ----
        {
            float z[4];
            #pragma unroll
            for (int g = 0; g < 4; g++) {
                int off = (g * 8 + eu) * 40 + eb;
                float s = gzc[g];
                #pragma unroll
                for (int w8 = 0; w8 < 8; w8++)
                    s += ((float*)(hsH + w8 * 1280))[off];
                z[g] = s;
            }
            float ig = fsigmoid(z[0]);
            float fg = fsigmoid(z[1]);
            float gv = ftanh(z[2]);
            float og = fsigmoid(z[3]);
            c = fg * c + ig * gv;
            float hval = og * ftanh(c);

            unsigned short hh, hl;
            split_bf16(hval, hh, hl);
            int gu = u0 + eu;
            int kp = gu >> 1;
            int half = gu & 1;
            ((unsigned short*)d_hpk[dir][nb][0])[(kp * 32 + eb) * 2 + half] = hh;
            ((unsigned short*)d_hpk[dir][nb][1])[(kp * 32 + eb) * 2 + half] = hl;
            if (t == TT - 1) d_hout[dir][eb * HHD + gu] = hval;
        }

        gzc[0] = gzn[0]; gzc[1] = gzn[1]; gzc[2] = gzn[2]; gzc[3] = gzn[3];

        // ---- atomic-free flag-array grid barrier (per direction) ----
        __syncthreads();
        if (tid == 0) {
            __threadfence();
            g_arr[dir][blk] = t + 1;
        }
        if (blk == 0) {
            if (tid < DBLK) {
                while (g_arr[dir][tid] < (unsigned)(t + 1)) { }
            }
            __syncthreads();
            if (tid == 0) {
                __threadfence();
                g_done[dir] = t + 1;
            }
        }
        if (tid == 0) {
            while (g_done[dir] < (unsigned)(t + 1)) { }
            __threadfence();
        }
        __syncthreads();
    }
}

// ---------------- final concat ----------------
__global__ void final_kernel(float* __restrict__ out) {
    int i = blockIdx.x * blockDim.x + threadIdx.x;
    if (i < BB * 2 * HHD) {
        int b = i >> 10;
        int j = i & 1023;
        out[i] = (j < HHD) ? d_hout[0][b * HHD + j]
                           : d_hout[1][b * HHD + j - HHD];
    }
}

// ---------------- launch ----------------
extern "C" void kernel_launch(void* const* d_in, const int* in_sizes, int n_in,
                              void* d_out, int out_size) {
    const float* x     = (const float*)d_in[0];
    const float* gamma = (const float*)d_in[1];
    const float* beta  = (const float*)d_in[2];
    const float* mean  = (const float*)d_in[3];
    const float* var   = (const float*)d_in[4];
    const float* Wf    = (const float*)d_in[5];
    const float* Uf    = (const float*)d_in[6];
    const float* bf    = (const float*)d_in[7];
    const float* Wb    = (const float*)d_in[8];
    const float* Ub    = (const float*)d_in[9];
    const float* bb    = (const float*)d_in[10];
    float* out = (float*)d_out;

    cudaFuncSetAttribute(lstm_persist, cudaFuncAttributeMaxDynamicSharedMemorySize,
                         LSTM_SMEM);

    bn_prep_kernel<<<1, 512>>>(gamma, beta, mean, var);

    split_x_kernel<<<MR * 256 / 256, 256>>>(x);
    split_w_kernel<<<2 * 256 * G4 / 256, 256>>>(Wf, Wb);

    dim3 ggrid(G4 / 128, MR / 128, 2);
    gemm_tc_kernel<<<ggrid, 256>>>(bf, bb);

    init_kernel<<<64, 256>>>();

    lstm_persist<<<NBLK, 256, LSTM_SMEM>>>(Uf, Ub);

    final_kernel<<<128, 256>>>(out);
}